// round 12
// baseline (speedup 1.0000x reference)
#include <cuda_runtime.h>
#include <cstdint>

#define T_STEPS 50
#define S_DIM   100
#define H_DIM   256
#define C_DIM   100
#define B_ROWS  4096
#define M_ROWS  32
#define N_CTA   (B_ROWS / M_ROWS)   // 128 CTAs, 1 per SM
#define NTHREADS 512
#define KC      32
#define WBUF    (256 * KC)          // one ring slot: 256 rows x 32 k floats (32KB)
#define N_PAIRS (49 * 10)           // global pair stream: 10 pairs(20 chunks)/step

typedef unsigned long long u64;

__device__ float    g_partials[N_CTA];
__device__ unsigned g_done;          // zero at load; last CTA resets each call

// ---------------- packed fp32x2 FMA (FFMA2) ----------------
__device__ __forceinline__ u64 ffma2(u64 a, u64 b, u64 c) {
    u64 d;
    asm("fma.rn.f32x2 %0, %1, %2, %3;" : "=l"(d) : "l"(a), "l"(b), "l"(c));
    return d;
}
__device__ __forceinline__ float fold2(u64 a) {
    float lo, hi;
    asm("mov.b64 {%0, %1}, %2;" : "=f"(lo), "=f"(hi) : "l"(a));
    return lo + hi;
}

// ---------------- cp.async helpers ----------------
__device__ __forceinline__ void cp16(float* dst_smem, const float* src) {
    unsigned d = (unsigned)__cvta_generic_to_shared(dst_smem);
    asm volatile("cp.async.ca.shared.global [%0], [%1], 16;" :: "r"(d), "l"(src));
}
__device__ __forceinline__ void cp_commit() {
    asm volatile("cp.async.commit_group;");
}
template<int N> __device__ __forceinline__ void cp_wait() {
    asm volatile("cp.async.wait_group %0;" :: "n"(N));
}

// ---------------- fused bias + LayerNorm + gamma/beta + relu ----------------
// 16 lanes per row: r = tid>>4 (0..31), l = tid&15.
__device__ __forceinline__ void ln_relu(const float* __restrict__ y,
                                        float* __restrict__ xo,
                                        const float* __restrict__ bias,
                                        const float* __restrict__ gamma,
                                        const float* __restrict__ beta,
                                        int r, int l) {
    float v[16];
    float sum = 0.f, sq = 0.f;
#pragma unroll
    for (int i = 0; i < 16; i++) {
        int h = l + (i << 4);
        float tv = y[r * 256 + h] + bias[h];
        v[i] = tv;
        sum += tv;
        sq = fmaf(tv, tv, sq);
    }
#pragma unroll
    for (int o = 8; o >= 1; o >>= 1) {
        sum += __shfl_xor_sync(0xffffffffu, sum, o);
        sq  += __shfl_xor_sync(0xffffffffu, sq, o);
    }
    float mean = sum * (1.f / 256.f);
    float var  = sq * (1.f / 256.f) - mean * mean;
    float rstd = rsqrtf(var + 1e-5f);
#pragma unroll
    for (int i = 0; i < 16; i++) {
        int h = l + (i << 4);
        float xn = (v[i] - mean) * rstd * gamma[h] + beta[h];
        xo[r * 256 + h] = fmaxf(xn, 0.f);
    }
}

__global__ void __launch_bounds__(NTHREADS, 1)
model_kernel(const float* __restrict__ s0, const float* __restrict__ prices,
             const float* __restrict__ W1, const float* __restrict__ b1,
             const float* __restrict__ g1, const float* __restrict__ be1,
             const float* __restrict__ W2, const float* __restrict__ b2,
             const float* __restrict__ g2, const float* __restrict__ be2,
             const float* __restrict__ Wo, const float* __restrict__ bo,
             float* __restrict__ out) {
    extern __shared__ float sm[];
    float* ring   = sm;                        // 4 slots * 8192 floats (128 KB)
    float* s_s    = sm + 4 * WBUF;             // 32 x 128 (cols 100..127 zero)
    float* s_x    = s_s + M_ROWS * 128;        // 32 x 256
    float* s_y    = s_x + M_ROWS * 256;        // 32 x 256 (cols 128..255 double as g3 scratch)
    float* s_cost = s_y + M_ROWS * 256;        // 32
    __shared__ int s_last;

    const int tid = threadIdx.x;
    const int b0  = blockIdx.x * M_ROWS;

    for (int i = tid; i < M_ROWS * 128; i += NTHREADS) {
        int r = i >> 7, c = i & 127;
        s_s[i] = (c < S_DIM) ? s0[(b0 + r) * S_DIM + c] : 0.f;
    }
    if (tid < M_ROWS) s_cost[tid] = 0.f;
    __syncthreads();

    // elementwise / LN map
    const int rr = tid >> 4;
    const int ll = tid & 15;
    // gemm1/2 map: kh = K half, rg = 8-row group, nq = col quad (0..63)
    const int kh = tid >> 8;
    const int rg = (tid >> 6) & 3;
    const int nq = tid & 63;
    const int m0 = rg << 3, n0 = nq << 2, sw = nq & 7;
    // gemm3 map: ks3 = K half, rg3 = 4-row group (0..7), nq3 = col quad (0..31)
    const int ks3 = tid >> 8;
    const int rg3 = (tid >> 5) & 7;
    const int nq3 = tid & 31;
    const int m03 = rg3 << 2, n03 = nq3 << 2, sw3 = nq3 & 7;

    // ---- global weight stream: pair p = 2 chunks (seq = 2p%20 within step) ----
    // seq 0..3: W1 chunks, 4..11: W2 chunks, 12..19: Wo chunks. slot = seq&3.
    auto issue_pair = [&](int p) {
        if (p >= N_PAIRS) { cp_commit(); return; }
        const int t2 = p / 10;
        const int k2 = p - t2 * 10;
        const int c  = tid & 7;
        const int nb = tid >> 3;                 // 0..63
#pragma unroll
        for (int h = 0; h < 2; h++) {
            int seq = (k2 << 1) + h;
            float* wb = ring + (seq & 3) * WBUF;
            if (seq < 4) {
                int cc = seq;
                int kg = cc * KC + (c << 2);
                if (kg < S_DIM) {
                    const float* src = W1 + t2 * (H_DIM * S_DIM) + kg;
#pragma unroll
                    for (int r = 0; r < 4; r++) {
                        int n   = nb + (r << 6);
                        int col = (c ^ ((n >> 2) & 7)) << 2;
                        cp16(wb + n * KC + col, src + n * S_DIM);
                    }
                }
            } else if (seq < 12) {
                int cc = seq - 4;
                const float* src = W2 + t2 * (H_DIM * H_DIM) + cc * KC + (c << 2);
#pragma unroll
                for (int r = 0; r < 4; r++) {
                    int n   = nb + (r << 6);
                    int col = (c ^ ((n >> 2) & 7)) << 2;
                    cp16(wb + n * KC + col, src + n * H_DIM);
                }
            } else {
                int cc = seq - 12;
                const float* src = Wo + t2 * (C_DIM * H_DIM) + cc * KC + (c << 2);
#pragma unroll
                for (int r = 0; r < 2; r++) {    // rows 0..127 (100..127 harmless overrun rows)
                    int n   = nb + (r << 6);
                    int col = (c ^ ((n >> 2) & 7)) << 2;
                    cp16(wb + n * KC + col, src + n * H_DIM);
                }
            }
        }
        cp_commit();   // one group per pair
    };

    issue_pair(0);     // prologue

    for (int t = 0; t < T_STEPS - 1; t++) {
        // prices into registers: consumed at step end (full-step latency hiding)
        float pr[7];
        {
            const float* prow = prices + ((size_t)(b0 + rr) * T_STEPS + t) * S_DIM;
#pragma unroll
            for (int i2 = 0; i2 < 7; i2++) {
                int idx = ll + (i2 << 4);
                pr[i2] = (idx < S_DIM) ? prow[idx] : 0.f;
            }
        }
        const int P0 = t * 10;

        // ---------------- gemm1: s(32x100 pad) @ W1^T (intervals 0..1) ----------------
        {
            u64 acc[8][4];
#pragma unroll
            for (int j = 0; j < 8; j++)
#pragma unroll
                for (int i = 0; i < 4; i++) acc[j][i] = 0ull;

#pragma unroll 1
            for (int iv = 0; iv < 2; iv++) {
                cp_wait<0>(); __syncthreads(); issue_pair(P0 + iv + 1);
#pragma unroll
                for (int h = 0; h < 2; h++) {
                    int cc = (iv << 1) + h;
                    const float* wb  = ring + (cc & 3) * WBUF;
                    const float* inb = s_s + cc * KC + (kh << 4);
#pragma unroll
                    for (int kk = 0; kk < 4; kk++) {
                        if (cc * KC + (kh << 4) + (kk << 2) < S_DIM) {
                            const int p = ((kh << 2) + kk) ^ sw;
                            ulonglong2 wv[4];
#pragma unroll
                            for (int i = 0; i < 4; i++)
                                wv[i] = *reinterpret_cast<const ulonglong2*>(
                                    wb + (n0 + i) * KC + (p << 2));
#pragma unroll
                            for (int j = 0; j < 8; j++) {
                                ulonglong2 xv = *reinterpret_cast<const ulonglong2*>(
                                    inb + (m0 + j) * 128 + (kk << 2));
#pragma unroll
                                for (int i = 0; i < 4; i++)
                                    acc[j][i] = ffma2(xv.x, wv[i].x, acc[j][i]);
#pragma unroll
                                for (int i = 0; i < 4; i++)
                                    acc[j][i] = ffma2(xv.y, wv[i].y, acc[j][i]);
                            }
                        }
                    }
                }
            }
            if (kh == 1) {
#pragma unroll
                for (int j = 0; j < 8; j++)
                    *reinterpret_cast<float4*>(s_y + (m0 + j) * 256 + n0) =
                        make_float4(fold2(acc[j][0]), fold2(acc[j][1]),
                                    fold2(acc[j][2]), fold2(acc[j][3]));
            }
            __syncthreads();
            if (kh == 0) {
#pragma unroll
                for (int j = 0; j < 8; j++) {
                    float4 o = *reinterpret_cast<const float4*>(s_y + (m0 + j) * 256 + n0);
                    o.x += fold2(acc[j][0]); o.y += fold2(acc[j][1]);
                    o.z += fold2(acc[j][2]); o.w += fold2(acc[j][3]);
                    *reinterpret_cast<float4*>(s_y + (m0 + j) * 256 + n0) = o;
                }
            }
            __syncthreads();
        }
        ln_relu(s_y, s_x, b1 + t * H_DIM, g1 + t * H_DIM, be1 + t * H_DIM, rr, ll);

        // ---------------- gemm2: x(32x256) @ W2^T (intervals 2..5) ----------------
        {
            u64 acc[8][4];
#pragma unroll
            for (int j = 0; j < 8; j++)
#pragma unroll
                for (int i = 0; i < 4; i++) acc[j][i] = 0ull;

#pragma unroll 1
            for (int iv = 2; iv < 6; iv++) {
                cp_wait<0>(); __syncthreads(); issue_pair(P0 + iv + 1);
#pragma unroll
                for (int h = 0; h < 2; h++) {
                    int cc  = ((iv - 2) << 1) + h;
                    int seq = 4 + cc;
                    const float* wb  = ring + (seq & 3) * WBUF;
                    const float* inb = s_x + cc * KC + (kh << 4);
#pragma unroll
                    for (int kk = 0; kk < 4; kk++) {
                        const int p = ((kh << 2) + kk) ^ sw;
                        ulonglong2 wv[4];
#pragma unroll
                        for (int i = 0; i < 4; i++)
                            wv[i] = *reinterpret_cast<const ulonglong2*>(
                                wb + (n0 + i) * KC + (p << 2));
#pragma unroll
                        for (int j = 0; j < 8; j++) {
                            ulonglong2 xv = *reinterpret_cast<const ulonglong2*>(
                                inb + (m0 + j) * 256 + (kk << 2));
#pragma unroll
                            for (int i = 0; i < 4; i++)
                                acc[j][i] = ffma2(xv.x, wv[i].x, acc[j][i]);
#pragma unroll
                            for (int i = 0; i < 4; i++)
                                acc[j][i] = ffma2(xv.y, wv[i].y, acc[j][i]);
                        }
                    }
                }
            }
            if (kh == 1) {
#pragma unroll
                for (int j = 0; j < 8; j++)
                    *reinterpret_cast<float4*>(s_y + (m0 + j) * 256 + n0) =
                        make_float4(fold2(acc[j][0]), fold2(acc[j][1]),
                                    fold2(acc[j][2]), fold2(acc[j][3]));
            }
            __syncthreads();
            if (kh == 0) {
#pragma unroll
                for (int j = 0; j < 8; j++) {
                    float4 o = *reinterpret_cast<const float4*>(s_y + (m0 + j) * 256 + n0);
                    o.x += fold2(acc[j][0]); o.y += fold2(acc[j][1]);
                    o.z += fold2(acc[j][2]); o.w += fold2(acc[j][3]);
                    *reinterpret_cast<float4*>(s_y + (m0 + j) * 256 + n0) = o;
                }
            }
            __syncthreads();
        }
        ln_relu(s_y, s_x, b2 + t * H_DIM, g2 + t * H_DIM, be2 + t * H_DIM, rr, ll);

        // ---------------- gemm3: x(32x256) @ Wo^T (intervals 6..9) ----------------
        {
            u64 acc[4][4];
#pragma unroll
            for (int j = 0; j < 4; j++)
#pragma unroll
                for (int i = 0; i < 4; i++) acc[j][i] = 0ull;

#pragma unroll 1
            for (int iv = 6; iv < 10; iv++) {
                cp_wait<0>(); __syncthreads(); issue_pair(P0 + iv + 1);
#pragma unroll
                for (int h = 0; h < 2; h++) {
                    int cc  = ((iv - 6) << 1) + h;
                    int seq = 12 + cc;
                    const float* wb  = ring + (seq & 3) * WBUF;
                    const float* inb = s_x + cc * KC + (ks3 << 4);
#pragma unroll
                    for (int kk = 0; kk < 4; kk++) {
                        const int p = ((ks3 << 2) + kk) ^ sw3;
                        ulonglong2 wv[4];
#pragma unroll
                        for (int i = 0; i < 4; i++)
                            wv[i] = *reinterpret_cast<const ulonglong2*>(
                                wb + (n03 + i) * KC + (p << 2));
#pragma unroll
                        for (int j = 0; j < 4; j++) {
                            ulonglong2 xv = *reinterpret_cast<const ulonglong2*>(
                                inb + (m03 + j) * 256 + (kk << 2));
#pragma unroll
                            for (int i = 0; i < 4; i++)
                                acc[j][i] = ffma2(xv.x, wv[i].x, acc[j][i]);
#pragma unroll
                            for (int i = 0; i < 4; i++)
                                acc[j][i] = ffma2(xv.y, wv[i].y, acc[j][i]);
                        }
                    }
                }
            }
            // K-combine via s_y cols 128..255 as scratch (ring is live with prefetch)
            if (ks3 == 1) {
#pragma unroll
                for (int j = 0; j < 4; j++)
                    *reinterpret_cast<float4*>(s_y + (m03 + j) * 256 + 128 + n03) =
                        make_float4(fold2(acc[j][0]), fold2(acc[j][1]),
                                    fold2(acc[j][2]), fold2(acc[j][3]));
            }
            __syncthreads();
            if (ks3 == 0) {
#pragma unroll
                for (int j = 0; j < 4; j++) {
                    float4 a = make_float4(fold2(acc[j][0]), fold2(acc[j][1]),
                                           fold2(acc[j][2]), fold2(acc[j][3]));
                    float4 b = *reinterpret_cast<const float4*>(
                        s_y + (m03 + j) * 256 + 128 + n03);
                    a.x += b.x; a.y += b.y; a.z += b.z; a.w += b.w;
                    *reinterpret_cast<float4*>(s_y + (m03 + j) * 256 + n03) = a;
                }
            }
            __syncthreads();
        }

        // elementwise: a = min(policy + bo, s); cost += p*a + 0.01*(p*a)^2; s -= a
        {
            const float* bo_t = bo + t * C_DIM;
            float part = 0.f;
#pragma unroll
            for (int i2 = 0; i2 < 7; i2++) {
                int idx = ll + (i2 << 4);
                if (idx < S_DIM) {
                    float sv = s_s[rr * 128 + idx];
                    float a  = fminf(s_y[rr * 256 + idx] + bo_t[idx], sv);
                    float pa = pr[i2] * a;
                    part += pa + 0.01f * pa * pa;
                    s_s[rr * 128 + idx] = sv - a;
                }
            }
#pragma unroll
            for (int o = 8; o >= 1; o >>= 1)
                part += __shfl_xor_sync(0xffffffffu, part, o);
            if (ll == 0) s_cost[rr] += part;
        }
        __syncthreads();   // s_s/s_y stable before next step
    }

    // terminal step: a = s
    {
        const float* p = prices + ((size_t)(b0 + rr) * T_STEPS + (T_STEPS - 1)) * S_DIM;
        float part = 0.f;
#pragma unroll
        for (int i2 = 0; i2 < 7; i2++) {
            int idx = ll + (i2 << 4);
            if (idx < S_DIM) {
                float sv = s_s[rr * 128 + idx];
                float pa = p[idx] * sv;
                part += pa + 0.01f * pa * pa;
            }
        }
#pragma unroll
        for (int o = 8; o >= 1; o >>= 1)
            part += __shfl_xor_sync(0xffffffffu, part, o);
        if (ll == 0) s_cost[rr] += part;
    }
    __syncthreads();

    // ---- CTA partial, then last-CTA-done final reduction (single-kernel stream) ----
    if (tid == 0) {
        float tot = 0.f;
#pragma unroll
        for (int r = 0; r < M_ROWS; r++) tot += s_cost[r];
        g_partials[blockIdx.x] = tot;
        __threadfence();
        unsigned old = atomicAdd(&g_done, 1u);
        s_last = (old == N_CTA - 1);
    }
    __syncthreads();
    if (s_last) {
        float v = (tid < N_CTA) ? g_partials[tid] : 0.f;
#pragma unroll
        for (int o = 16; o >= 1; o >>= 1)
            v += __shfl_xor_sync(0xffffffffu, v, o);
        // 128 live lanes -> 4 warp leaders; combine via s_cost scratch
        if (tid < N_CTA && (tid & 31) == 0) s_cost[tid >> 5] = v;
        __syncthreads();
        if (tid == 0) {
            float tot = s_cost[0] + s_cost[1] + s_cost[2] + s_cost[3];
            out[0] = tot * (1.f / (float)B_ROWS);
            g_done = 0;          // reset for next graph replay
        }
    }
}

extern "C" void kernel_launch(void* const* d_in, const int* in_sizes, int n_in,
                              void* d_out, int out_size) {
    const float* s0     = (const float*)d_in[0];
    const float* prices = (const float*)d_in[1];
    const float* W1     = (const float*)d_in[2];
    const float* b1     = (const float*)d_in[3];
    const float* g1     = (const float*)d_in[4];
    const float* be1    = (const float*)d_in[5];
    const float* W2     = (const float*)d_in[6];
    const float* b2     = (const float*)d_in[7];
    const float* g2     = (const float*)d_in[8];
    const float* be2    = (const float*)d_in[9];
    const float* Wo     = (const float*)d_in[10];
    const float* bo     = (const float*)d_in[11];

    size_t smem = (size_t)(4 * WBUF + M_ROWS * 128 + 2 * M_ROWS * 256 + M_ROWS)
                  * sizeof(float);
    cudaFuncSetAttribute(model_kernel, cudaFuncAttributeMaxDynamicSharedMemorySize, (int)smem);
    model_kernel<<<N_CTA, NTHREADS, smem>>>(s0, prices, W1, b1, g1, be1,
                                            W2, b2, g2, be2, Wo, bo,
                                            (float*)d_out);
}

// round 13
// speedup vs baseline: 1.0071x; 1.0071x over previous
#include <cuda_runtime.h>
#include <cstdint>

#define T_STEPS 50
#define S_DIM   100
#define H_DIM   256
#define C_DIM   100
#define B_ROWS  4096
#define M_ROWS  32
#define N_CTA   (B_ROWS / M_ROWS)   // 128 CTAs, 1 per SM
#define NTHREADS 512
#define KC      32
#define WBUF    (256 * KC)          // one ring slot: 256 rows x 32 k floats (32KB)
#define N_PAIRS (49 * 10)           // global pair stream: 10 pairs(20 chunks)/step

typedef unsigned long long u64;

__device__ float    g_partials[N_CTA];
__device__ unsigned g_done;          // zero at load; last CTA resets each call

// ---------------- packed fp32x2 FMA (FFMA2) ----------------
__device__ __forceinline__ u64 ffma2(u64 a, u64 b, u64 c) {
    u64 d;
    asm("fma.rn.f32x2 %0, %1, %2, %3;" : "=l"(d) : "l"(a), "l"(b), "l"(c));
    return d;
}
__device__ __forceinline__ float fold2(u64 a) {
    float lo, hi;
    asm("mov.b64 {%0, %1}, %2;" : "=f"(lo), "=f"(hi) : "l"(a));
    return lo + hi;
}

// ---------------- cp.async helpers ----------------
__device__ __forceinline__ void cp16(float* dst_smem, const float* src) {
    unsigned d = (unsigned)__cvta_generic_to_shared(dst_smem);
    asm volatile("cp.async.ca.shared.global [%0], [%1], 16;" :: "r"(d), "l"(src));
}
__device__ __forceinline__ void cp_commit() {
    asm volatile("cp.async.commit_group;");
}
template<int N> __device__ __forceinline__ void cp_wait() {
    asm volatile("cp.async.wait_group %0;" :: "n"(N));
}

// ---------------- fused bias + LayerNorm + gamma/beta + relu ----------------
// 16 lanes per row: r = tid>>4 (0..31), l = tid&15.
__device__ __forceinline__ void ln_relu(const float* __restrict__ y,
                                        float* __restrict__ xo,
                                        const float* __restrict__ bias,
                                        const float* __restrict__ gamma,
                                        const float* __restrict__ beta,
                                        int r, int l) {
    float v[16];
    float sum = 0.f, sq = 0.f;
#pragma unroll
    for (int i = 0; i < 16; i++) {
        int h = l + (i << 4);
        float tv = y[r * 256 + h] + bias[h];
        v[i] = tv;
        sum += tv;
        sq = fmaf(tv, tv, sq);
    }
#pragma unroll
    for (int o = 8; o >= 1; o >>= 1) {
        sum += __shfl_xor_sync(0xffffffffu, sum, o);
        sq  += __shfl_xor_sync(0xffffffffu, sq, o);
    }
    float mean = sum * (1.f / 256.f);
    float var  = sq * (1.f / 256.f) - mean * mean;
    float rstd = rsqrtf(var + 1e-5f);
#pragma unroll
    for (int i = 0; i < 16; i++) {
        int h = l + (i << 4);
        float xn = (v[i] - mean) * rstd * gamma[h] + beta[h];
        xo[r * 256 + h] = fmaxf(xn, 0.f);
    }
}

__global__ void __launch_bounds__(NTHREADS, 1)
model_kernel(const float* __restrict__ s0, const float* __restrict__ prices,
             const float* __restrict__ W1, const float* __restrict__ b1,
             const float* __restrict__ g1, const float* __restrict__ be1,
             const float* __restrict__ W2, const float* __restrict__ b2,
             const float* __restrict__ g2, const float* __restrict__ be2,
             const float* __restrict__ Wo, const float* __restrict__ bo,
             float* __restrict__ out) {
    extern __shared__ float sm[];
    float* ring   = sm;                        // 4 slots * 8192 floats (128 KB)
    float* s_s    = sm + 4 * WBUF;             // 32 x 128 (cols 100..127 zero)
    float* s_x    = s_s + M_ROWS * 128;        // 32 x 256
    float* s_y    = s_x + M_ROWS * 256;        // 32 x 256 (cols 128..255 double as g3 scratch)
    float* s_cost = s_y + M_ROWS * 256;        // 32
    __shared__ int s_last;

    const int tid = threadIdx.x;
    const int b0  = blockIdx.x * M_ROWS;

    for (int i = tid; i < M_ROWS * 128; i += NTHREADS) {
        int r = i >> 7, c = i & 127;
        s_s[i] = (c < S_DIM) ? s0[(b0 + r) * S_DIM + c] : 0.f;
    }
    if (tid < M_ROWS) s_cost[tid] = 0.f;
    __syncthreads();

    // elementwise / LN map
    const int rr = tid >> 4;
    const int ll = tid & 15;
    // gemm1/2 map: kh = K half, rg = 8-row group, nq = col quad (0..63)
    const int kh = tid >> 8;
    const int rg = (tid >> 6) & 3;
    const int nq = tid & 63;
    const int m0 = rg << 3, n0 = nq << 2, sw = nq & 7;
    // gemm3 map: ks3 = K half, rg3 = 4-row group (0..7), nq3 = col quad (0..31)
    const int ks3 = tid >> 8;
    const int rg3 = (tid >> 5) & 7;
    const int nq3 = tid & 31;
    const int m03 = rg3 << 2, n03 = nq3 << 2, sw3 = nq3 & 7;

    // ---- global weight stream: pair p = 2 chunks (seq = 2p%20 within step) ----
    // seq 0..3: W1 chunks, 4..11: W2 chunks, 12..19: Wo chunks. slot = seq&3.
    auto issue_pair = [&](int p) {
        if (p >= N_PAIRS) { cp_commit(); return; }
        const int t2 = p / 10;
        const int k2 = p - t2 * 10;
        const int c  = tid & 7;
        const int nb = tid >> 3;                 // 0..63
#pragma unroll
        for (int h = 0; h < 2; h++) {
            int seq = (k2 << 1) + h;
            float* wb = ring + (seq & 3) * WBUF;
            if (seq < 4) {
                int cc = seq;
                int kg = cc * KC + (c << 2);
                if (kg < S_DIM) {
                    const float* src = W1 + t2 * (H_DIM * S_DIM) + kg;
#pragma unroll
                    for (int r = 0; r < 4; r++) {
                        int n   = nb + (r << 6);
                        int col = (c ^ ((n >> 2) & 7)) << 2;
                        cp16(wb + n * KC + col, src + n * S_DIM);
                    }
                }
            } else if (seq < 12) {
                int cc = seq - 4;
                const float* src = W2 + t2 * (H_DIM * H_DIM) + cc * KC + (c << 2);
#pragma unroll
                for (int r = 0; r < 4; r++) {
                    int n   = nb + (r << 6);
                    int col = (c ^ ((n >> 2) & 7)) << 2;
                    cp16(wb + n * KC + col, src + n * H_DIM);
                }
            } else {
                int cc = seq - 12;
                const float* src = Wo + t2 * (C_DIM * H_DIM) + cc * KC + (c << 2);
#pragma unroll
                for (int r = 0; r < 2; r++) {    // rows 0..127 (100..127 harmless overrun rows)
                    int n   = nb + (r << 6);
                    int col = (c ^ ((n >> 2) & 7)) << 2;
                    cp16(wb + n * KC + col, src + n * H_DIM);
                }
            }
        }
        cp_commit();   // one group per pair
    };

    issue_pair(0);     // prologue

    for (int t = 0; t < T_STEPS - 1; t++) {
        // prices into registers: consumed at step end (full-step latency hiding)
        float pr[7];
        {
            const float* prow = prices + ((size_t)(b0 + rr) * T_STEPS + t) * S_DIM;
#pragma unroll
            for (int i2 = 0; i2 < 7; i2++) {
                int idx = ll + (i2 << 4);
                pr[i2] = (idx < S_DIM) ? prow[idx] : 0.f;
            }
        }
        const int P0 = t * 10;

        // ---------------- gemm1: s(32x100 pad) @ W1^T (intervals 0..1) ----------------
        {
            u64 acc[8][4];
#pragma unroll
            for (int j = 0; j < 8; j++)
#pragma unroll
                for (int i = 0; i < 4; i++) acc[j][i] = 0ull;

#pragma unroll 1
            for (int iv = 0; iv < 2; iv++) {
                cp_wait<0>(); __syncthreads(); issue_pair(P0 + iv + 1);
#pragma unroll
                for (int h = 0; h < 2; h++) {
                    int cc = (iv << 1) + h;
                    const float* wb  = ring + (cc & 3) * WBUF;
                    const float* inb = s_s + cc * KC + (kh << 4);
#pragma unroll
                    for (int kk = 0; kk < 4; kk++) {
                        if (cc * KC + (kh << 4) + (kk << 2) < S_DIM) {
                            const int p = ((kh << 2) + kk) ^ sw;
                            ulonglong2 wv[4];
#pragma unroll
                            for (int i = 0; i < 4; i++)
                                wv[i] = *reinterpret_cast<const ulonglong2*>(
                                    wb + (n0 + i) * KC + (p << 2));
#pragma unroll
                            for (int j = 0; j < 8; j++) {
                                ulonglong2 xv = *reinterpret_cast<const ulonglong2*>(
                                    inb + (m0 + j) * 128 + (kk << 2));
#pragma unroll
                                for (int i = 0; i < 4; i++)
                                    acc[j][i] = ffma2(xv.x, wv[i].x, acc[j][i]);
#pragma unroll
                                for (int i = 0; i < 4; i++)
                                    acc[j][i] = ffma2(xv.y, wv[i].y, acc[j][i]);
                            }
                        }
                    }
                }
            }
            if (kh == 1) {
#pragma unroll
                for (int j = 0; j < 8; j++)
                    *reinterpret_cast<float4*>(s_y + (m0 + j) * 256 + n0) =
                        make_float4(fold2(acc[j][0]), fold2(acc[j][1]),
                                    fold2(acc[j][2]), fold2(acc[j][3]));
            }
            __syncthreads();
            if (kh == 0) {
#pragma unroll
                for (int j = 0; j < 8; j++) {
                    float4 o = *reinterpret_cast<const float4*>(s_y + (m0 + j) * 256 + n0);
                    o.x += fold2(acc[j][0]); o.y += fold2(acc[j][1]);
                    o.z += fold2(acc[j][2]); o.w += fold2(acc[j][3]);
                    *reinterpret_cast<float4*>(s_y + (m0 + j) * 256 + n0) = o;
                }
            }
            __syncthreads();
        }
        ln_relu(s_y, s_x, b1 + t * H_DIM, g1 + t * H_DIM, be1 + t * H_DIM, rr, ll);

        // ---------------- gemm2: x(32x256) @ W2^T (intervals 2..5) ----------------
        {
            u64 acc[8][4];
#pragma unroll
            for (int j = 0; j < 8; j++)
#pragma unroll
                for (int i = 0; i < 4; i++) acc[j][i] = 0ull;

#pragma unroll 1
            for (int iv = 2; iv < 6; iv++) {
                cp_wait<0>(); __syncthreads(); issue_pair(P0 + iv + 1);
#pragma unroll
                for (int h = 0; h < 2; h++) {
                    int cc  = ((iv - 2) << 1) + h;
                    int seq = 4 + cc;
                    const float* wb  = ring + (seq & 3) * WBUF;
                    const float* inb = s_x + cc * KC + (kh << 4);
#pragma unroll
                    for (int kk = 0; kk < 4; kk++) {
                        const int p = ((kh << 2) + kk) ^ sw;
                        ulonglong2 wv[4];
#pragma unroll
                        for (int i = 0; i < 4; i++)
                            wv[i] = *reinterpret_cast<const ulonglong2*>(
                                wb + (n0 + i) * KC + (p << 2));
#pragma unroll
                        for (int j = 0; j < 8; j++) {
                            ulonglong2 xv = *reinterpret_cast<const ulonglong2*>(
                                inb + (m0 + j) * 256 + (kk << 2));
#pragma unroll
                            for (int i = 0; i < 4; i++)
                                acc[j][i] = ffma2(xv.x, wv[i].x, acc[j][i]);
#pragma unroll
                            for (int i = 0; i < 4; i++)
                                acc[j][i] = ffma2(xv.y, wv[i].y, acc[j][i]);
                        }
                    }
                }
            }
            if (kh == 1) {
#pragma unroll
                for (int j = 0; j < 8; j++)
                    *reinterpret_cast<float4*>(s_y + (m0 + j) * 256 + n0) =
                        make_float4(fold2(acc[j][0]), fold2(acc[j][1]),
                                    fold2(acc[j][2]), fold2(acc[j][3]));
            }
            __syncthreads();
            if (kh == 0) {
#pragma unroll
                for (int j = 0; j < 8; j++) {
                    float4 o = *reinterpret_cast<const float4*>(s_y + (m0 + j) * 256 + n0);
                    o.x += fold2(acc[j][0]); o.y += fold2(acc[j][1]);
                    o.z += fold2(acc[j][2]); o.w += fold2(acc[j][3]);
                    *reinterpret_cast<float4*>(s_y + (m0 + j) * 256 + n0) = o;
                }
            }
            __syncthreads();
        }
        ln_relu(s_y, s_x, b2 + t * H_DIM, g2 + t * H_DIM, be2 + t * H_DIM, rr, ll);

        // ---------------- gemm3: x(32x256) @ Wo^T (intervals 6..9) ----------------
        {
            u64 acc[4][4];
#pragma unroll
            for (int j = 0; j < 4; j++)
#pragma unroll
                for (int i = 0; i < 4; i++) acc[j][i] = 0ull;

#pragma unroll 1
            for (int iv = 6; iv < 10; iv++) {
                cp_wait<0>(); __syncthreads(); issue_pair(P0 + iv + 1);
#pragma unroll
                for (int h = 0; h < 2; h++) {
                    int cc  = ((iv - 6) << 1) + h;
                    int seq = 12 + cc;
                    const float* wb  = ring + (seq & 3) * WBUF;
                    const float* inb = s_x + cc * KC + (ks3 << 4);
#pragma unroll
                    for (int kk = 0; kk < 4; kk++) {
                        const int p = ((ks3 << 2) + kk) ^ sw3;
                        ulonglong2 wv[4];
#pragma unroll
                        for (int i = 0; i < 4; i++)
                            wv[i] = *reinterpret_cast<const ulonglong2*>(
                                wb + (n03 + i) * KC + (p << 2));
#pragma unroll
                        for (int j = 0; j < 4; j++) {
                            ulonglong2 xv = *reinterpret_cast<const ulonglong2*>(
                                inb + (m03 + j) * 256 + (kk << 2));
#pragma unroll
                            for (int i = 0; i < 4; i++)
                                acc[j][i] = ffma2(xv.x, wv[i].x, acc[j][i]);
#pragma unroll
                            for (int i = 0; i < 4; i++)
                                acc[j][i] = ffma2(xv.y, wv[i].y, acc[j][i]);
                        }
                    }
                }
            }
            // K-combine via s_y cols 128..255 as scratch (ring is live with prefetch)
            if (ks3 == 1) {
#pragma unroll
                for (int j = 0; j < 4; j++)
                    *reinterpret_cast<float4*>(s_y + (m03 + j) * 256 + 128 + n03) =
                        make_float4(fold2(acc[j][0]), fold2(acc[j][1]),
                                    fold2(acc[j][2]), fold2(acc[j][3]));
            }
            __syncthreads();
            if (ks3 == 0) {
#pragma unroll
                for (int j = 0; j < 4; j++) {
                    float4 a = make_float4(fold2(acc[j][0]), fold2(acc[j][1]),
                                           fold2(acc[j][2]), fold2(acc[j][3]));
                    float4 b = *reinterpret_cast<const float4*>(
                        s_y + (m03 + j) * 256 + 128 + n03);
                    a.x += b.x; a.y += b.y; a.z += b.z; a.w += b.w;
                    *reinterpret_cast<float4*>(s_y + (m03 + j) * 256 + n03) = a;
                }
            }
            __syncthreads();
        }

        // elementwise: a = min(policy + bo, s); cost += p*a + 0.01*(p*a)^2; s -= a
        {
            const float* bo_t = bo + t * C_DIM;
            float part = 0.f;
#pragma unroll
            for (int i2 = 0; i2 < 7; i2++) {
                int idx = ll + (i2 << 4);
                if (idx < S_DIM) {
                    float sv = s_s[rr * 128 + idx];
                    float a  = fminf(s_y[rr * 256 + idx] + bo_t[idx], sv);
                    float pa = pr[i2] * a;
                    part += pa + 0.01f * pa * pa;
                    s_s[rr * 128 + idx] = sv - a;
                }
            }
#pragma unroll
            for (int o = 8; o >= 1; o >>= 1)
                part += __shfl_xor_sync(0xffffffffu, part, o);
            if (ll == 0) s_cost[rr] += part;
        }
        __syncthreads();   // s_s/s_y stable before next step
    }

    // terminal step: a = s
    {
        const float* p = prices + ((size_t)(b0 + rr) * T_STEPS + (T_STEPS - 1)) * S_DIM;
        float part = 0.f;
#pragma unroll
        for (int i2 = 0; i2 < 7; i2++) {
            int idx = ll + (i2 << 4);
            if (idx < S_DIM) {
                float sv = s_s[rr * 128 + idx];
                float pa = p[idx] * sv;
                part += pa + 0.01f * pa * pa;
            }
        }
#pragma unroll
        for (int o = 8; o >= 1; o >>= 1)
            part += __shfl_xor_sync(0xffffffffu, part, o);
        if (ll == 0) s_cost[rr] += part;
    }
    __syncthreads();

    // ---- CTA partial, then last-CTA-done final reduction (single-kernel stream) ----
    if (tid == 0) {
        float tot = 0.f;
#pragma unroll
        for (int r = 0; r < M_ROWS; r++) tot += s_cost[r];
        g_partials[blockIdx.x] = tot;
        __threadfence();
        unsigned old = atomicAdd(&g_done, 1u);
        s_last = (old == N_CTA - 1);
    }
    __syncthreads();
    if (s_last) {
        float v = (tid < N_CTA) ? g_partials[tid] : 0.f;
#pragma unroll
        for (int o = 16; o >= 1; o >>= 1)
            v += __shfl_xor_sync(0xffffffffu, v, o);
        // 128 live lanes -> 4 warp leaders; combine via s_cost scratch
        if (tid < N_CTA && (tid & 31) == 0) s_cost[tid >> 5] = v;
        __syncthreads();
        if (tid == 0) {
            float tot = s_cost[0] + s_cost[1] + s_cost[2] + s_cost[3];
            out[0] = tot * (1.f / (float)B_ROWS);
            g_done = 0;          // reset for next graph replay
        }
    }
}

extern "C" void kernel_launch(void* const* d_in, const int* in_sizes, int n_in,
                              void* d_out, int out_size) {
    const float* s0     = (const float*)d_in[0];
    const float* prices = (const float*)d_in[1];
    const float* W1     = (const float*)d_in[2];
    const float* b1     = (const float*)d_in[3];
    const float* g1     = (const float*)d_in[4];
    const float* be1    = (const float*)d_in[5];
    const float* W2     = (const float*)d_in[6];
    const float* b2     = (const float*)d_in[7];
    const float* g2     = (const float*)d_in[8];
    const float* be2    = (const float*)d_in[9];
    const float* Wo     = (const float*)d_in[10];
    const float* bo     = (const float*)d_in[11];

    size_t smem = (size_t)(4 * WBUF + M_ROWS * 128 + 2 * M_ROWS * 256 + M_ROWS)
                  * sizeof(float);
    cudaFuncSetAttribute(model_kernel, cudaFuncAttributeMaxDynamicSharedMemorySize, (int)smem);
    model_kernel<<<N_CTA, NTHREADS, smem>>>(s0, prices, W1, b1, g1, be1,
                                            W2, b2, g2, be2, Wo, bo,
                                            (float*)d_out);
}

// round 15
// speedup vs baseline: 1.3959x; 1.3861x over previous
#include <cuda_runtime.h>
#include <cuda_bf16.h>
#include <cstdint>

#define T_STEPS 50
#define S_DIM   100
#define H_DIM   256
#define B_ROWS  4096
#define M_ROWS  32
#define N_CTA   128
#define NTHREADS 512
#define UNITS_PER_STEP 39            // 7 (L1) + 16 (L2) + 16 (L3) ksteps
#define N_UNITS_TOT (49 * UNITS_PER_STEP)
#define SLOT 24576                   // ring slot bytes (hi 12KB + lo 12KB)
#define WROWB 48                     // W row stride bytes (16 bf16 + pad)
#define XSTRIDE 264                  // activation tile row stride (bf16 elems)
#define YSTRIDE 260                  // y row stride (f32 elems)

// ---- smem byte map ----
#define SM_RING 0                    // 4 * 24576
#define SM_XA_H 98304                // s tiles hi (32 x 264 bf16)
#define SM_XA_L 115200
#define SM_XB_H 132096               // x tiles hi
#define SM_XB_L 148992
#define SM_Y    165888               // 32 x 260 f32
#define SM_SS   199168               // 32 x 128 f32
#define SM_COST 215552
#define SM_LAST 215680
#define SM_TOTAL 215696

__device__ unsigned char g_wbuf[(size_t)N_UNITS_TOT * SLOT];
__device__ float    g_partials[N_CTA];
__device__ unsigned g_done;

// ---------------- helpers ----------------
__device__ __forceinline__ uint32_t smem_u32(const void* p) {
    uint32_t a;
    asm("{ .reg .u64 t; cvta.to.shared.u64 t, %1; cvt.u32.u64 %0, t; }" : "=r"(a) : "l"(p));
    return a;
}
__device__ __forceinline__ void cp16(void* dst_smem, const void* src) {
    unsigned d = (unsigned)__cvta_generic_to_shared(dst_smem);
    asm volatile("cp.async.ca.shared.global [%0], [%1], 16;" :: "r"(d), "l"(src));
}
__device__ __forceinline__ void cp_commit() { asm volatile("cp.async.commit_group;"); }
template<int N> __device__ __forceinline__ void cp_wait() {
    asm volatile("cp.async.wait_group %0;" :: "n"(N));
}
__device__ __forceinline__ void split2(float f0, float f1, unsigned& h, unsigned& l) {
    asm("cvt.rn.bf16x2.f32 %0, %1, %2;" : "=r"(h) : "f"(f1), "f"(f0));
    __nv_bfloat162 hb = *reinterpret_cast<__nv_bfloat162*>(&h);
    float e0 = f0 - __bfloat162float(hb.x);
    float e1 = f1 - __bfloat162float(hb.y);
    asm("cvt.rn.bf16x2.f32 %0, %1, %2;" : "=r"(l) : "f"(e1), "f"(e0));
}
__device__ __forceinline__ void ldsm4(uint32_t* r, uint32_t a) {
    asm volatile("ldmatrix.sync.aligned.m8n8.x4.shared.b16 {%0,%1,%2,%3}, [%4];"
        : "=r"(r[0]), "=r"(r[1]), "=r"(r[2]), "=r"(r[3]) : "r"(a));
}
__device__ __forceinline__ void mma16816(float* d, const uint32_t* a, uint32_t b0, uint32_t b1) {
    asm volatile(
        "mma.sync.aligned.m16n8k16.row.col.f32.bf16.bf16.f32 "
        "{%0,%1,%2,%3}, {%4,%5,%6,%7}, {%8,%9}, {%0,%1,%2,%3};"
        : "+f"(d[0]), "+f"(d[1]), "+f"(d[2]), "+f"(d[3])
        : "r"(a[0]), "r"(a[1]), "r"(a[2]), "r"(a[3]), "r"(b0), "r"(b1));
}

// ---------------- prep: fp32 weights -> bf16 hi/lo unit stream ----------------
// unit u = t*39 + j.  j 0..6: W1 kstep j; 7..22: W2 kstep j-7; 23..38: Wo kstep j-23.
// Unit layout: hi block rows*48B at 0, lo block at rows*48.  rows=256 (L1/L2), 128 (L3).
__global__ void prep_kernel(const float* __restrict__ W1, const float* __restrict__ W2,
                            const float* __restrict__ Wo) {
    int u = blockIdx.x;
    int t = u / UNITS_PER_STEP, j = u % UNITS_PER_STEP;
    const float* src; int rstride, kbase, kmax, rows, rmax;
    if (j < 7)       { src = W1 + (size_t)t * H_DIM * S_DIM; rstride = S_DIM; kbase = j * 16;        kmax = S_DIM; rows = 256; rmax = 256; }
    else if (j < 23) { src = W2 + (size_t)t * H_DIM * H_DIM; rstride = H_DIM; kbase = (j - 7) * 16;  kmax = H_DIM; rows = 256; rmax = 256; }
    else             { src = Wo + (size_t)t * S_DIM * H_DIM; rstride = H_DIM; kbase = (j - 23) * 16; kmax = H_DIM; rows = 128; rmax = 100; }
    unsigned char* dst = g_wbuf + (size_t)u * SLOT;
    int lo_off = rows * WROWB;
    for (int n = threadIdx.x; n < rows; n += blockDim.x) {
        float v[16];
#pragma unroll
        for (int i = 0; i < 16; i++) {
            int gk = kbase + i;
            v[i] = (n < rmax && gk < kmax) ? src[(size_t)n * rstride + gk] : 0.f;
        }
        unsigned hi[8], lo[8];
#pragma unroll
        for (int i = 0; i < 8; i++) split2(v[2 * i], v[2 * i + 1], hi[i], lo[i]);
        *(uint4*)(dst + n * WROWB)          = make_uint4(hi[0], hi[1], hi[2], hi[3]);
        *(uint4*)(dst + n * WROWB + 16)     = make_uint4(hi[4], hi[5], hi[6], hi[7]);
        *(uint4*)(dst + lo_off + n * WROWB)      = make_uint4(lo[0], lo[1], lo[2], lo[3]);
        *(uint4*)(dst + lo_off + n * WROWB + 16) = make_uint4(lo[4], lo[5], lo[6], lo[7]);
    }
}

// ---------------- unit prefetch (ring slot u&3) ----------------
__device__ __forceinline__ void prefetch_unit(char* smc, int u, int tid) {
    if (u < N_UNITS_TOT) {
        int j = u % UNITS_PER_STEP;
        int bytes = (j < 23) ? 24576 : 12288;
        const char* s = (const char*)g_wbuf + (size_t)u * SLOT;
        char* d = smc + SM_RING + (u & 3) * SLOT;
        for (int off = tid * 16; off < bytes; off += NTHREADS * 16)
            cp16(d + off, s + off);
    }
    cp_commit();
}

// ---------------- one kstep unit, 4 n8-tiles per warp (L1/L2) ----------------
__device__ __forceinline__ void unit4(char* smc, uint32_t sb, int tid, int u, int ks,
                                      uint32_t xh, uint32_t xl, float acc[4][4]) {
    cp_wait<2>(); __syncthreads();
    prefetch_unit(smc, u + 3, tid);
    const int w = tid >> 5, l = tid & 31;
    const int mg = w & 1, n0 = (w >> 1) << 5;
    const uint32_t wb = sb + SM_RING + (u & 3) * SLOT;
    const uint32_t lo_off = 256 * WROWB;
    // A fragments (hi/lo)
    int m  = (mg << 4) + (l & 15);
    int ke = (ks << 4) + ((l >> 4) << 3);
    uint32_t xo = (uint32_t)(m * XSTRIDE + ke) * 2;
    uint32_t ah[4], al[4];
    ldsm4(ah, xh + xo);
    ldsm4(al, xl + xo);
    // B fragments: 4 n8 tiles, hi and lo
    int nb = (((l >> 4) & 1) << 3) + (l & 7);
    uint32_t bo = (uint32_t)(n0 + nb) * WROWB + (((l >> 3) & 1) << 4);
    uint32_t bh[8], bl[8];
    ldsm4(bh,     wb + bo);
    ldsm4(bh + 4, wb + bo + 16 * WROWB);
    ldsm4(bl,     wb + lo_off + bo);
    ldsm4(bl + 4, wb + lo_off + bo + 16 * WROWB);
#pragma unroll
    for (int i = 0; i < 4; i++) {
        mma16816(acc[i], ah, bh[2 * i], bh[2 * i + 1]);
        mma16816(acc[i], ah, bl[2 * i], bl[2 * i + 1]);
        mma16816(acc[i], al, bh[2 * i], bh[2 * i + 1]);
    }
}

// ---------------- one kstep unit, 2 n8-tiles per warp (L3, 128 W rows) ----------------
__device__ __forceinline__ void unit2(char* smc, uint32_t sb, int tid, int u, int ks,
                                      uint32_t xh, uint32_t xl, float acc[2][4]) {
    cp_wait<2>(); __syncthreads();
    prefetch_unit(smc, u + 3, tid);
    const int w = tid >> 5, l = tid & 31;
    const int mg = w & 1, n0 = (w >> 1) << 4;
    const uint32_t wb = sb + SM_RING + (u & 3) * SLOT;
    const uint32_t lo_off = 128 * WROWB;
    int m  = (mg << 4) + (l & 15);
    int ke = (ks << 4) + ((l >> 4) << 3);
    uint32_t xo = (uint32_t)(m * XSTRIDE + ke) * 2;
    uint32_t ah[4], al[4];
    ldsm4(ah, xh + xo);
    ldsm4(al, xl + xo);
    int nb = (((l >> 4) & 1) << 3) + (l & 7);
    uint32_t bo = (uint32_t)(n0 + nb) * WROWB + (((l >> 3) & 1) << 4);
    uint32_t bh[4], bl[4];
    ldsm4(bh, wb + bo);
    ldsm4(bl, wb + lo_off + bo);
#pragma unroll
    for (int i = 0; i < 2; i++) {
        mma16816(acc[i], ah, bh[2 * i], bh[2 * i + 1]);
        mma16816(acc[i], ah, bl[2 * i], bl[2 * i + 1]);
        mma16816(acc[i], al, bh[2 * i], bh[2 * i + 1]);
    }
}

__device__ __forceinline__ void store_acc4(float* y, int tid, float acc[4][4]) {
    int w = tid >> 5, l = tid & 31;
    int m = ((w & 1) << 4) + (l >> 2);
    int n0 = (w >> 1) << 5;
    int c = (l & 3) << 1;
#pragma unroll
    for (int i = 0; i < 4; i++) {
        int n = n0 + (i << 3) + c;
        y[m * YSTRIDE + n] = acc[i][0];       y[m * YSTRIDE + n + 1] = acc[i][1];
        y[(m + 8) * YSTRIDE + n] = acc[i][2]; y[(m + 8) * YSTRIDE + n + 1] = acc[i][3];
    }
}
__device__ __forceinline__ void store_acc2(float* y, int tid, float acc[2][4]) {
    int w = tid >> 5, l = tid & 31;
    int m = ((w & 1) << 4) + (l >> 2);
    int n0 = (w >> 1) << 4;
    int c = (l & 3) << 1;
#pragma unroll
    for (int i = 0; i < 2; i++) {
        int n = n0 + (i << 3) + c;
        y[m * YSTRIDE + n] = acc[i][0];       y[m * YSTRIDE + n + 1] = acc[i][1];
        y[(m + 8) * YSTRIDE + n] = acc[i][2]; y[(m + 8) * YSTRIDE + n + 1] = acc[i][3];
    }
}

// LN + relu from y (fp32) -> XB bf16 hi/lo tiles
__device__ __forceinline__ void epi_ln(char* smc, int tid,
                                       const float* __restrict__ bias,
                                       const float* __restrict__ gam,
                                       const float* __restrict__ bet) {
    float* y = (float*)(smc + SM_Y);
    int rr = tid >> 4, ll = tid & 15;
    float v[16], sum = 0.f, sq = 0.f;
#pragma unroll
    for (int i = 0; i < 16; i++) {
        int h = ll + (i << 4);
        float tv = y[rr * YSTRIDE + h] + bias[h];
        v[i] = tv; sum += tv; sq = fmaf(tv, tv, sq);
    }
#pragma unroll
    for (int o = 8; o >= 1; o >>= 1) {
        sum += __shfl_xor_sync(0xffffffffu, sum, o);
        sq  += __shfl_xor_sync(0xffffffffu, sq, o);
    }
    float mean = sum * (1.f / 256.f);
    float var  = sq * (1.f / 256.f) - mean * mean;
    float rstd = rsqrtf(var + 1e-5f);
    __nv_bfloat16* xh = (__nv_bfloat16*)(smc + SM_XB_H);
    __nv_bfloat16* xl = (__nv_bfloat16*)(smc + SM_XB_L);
#pragma unroll
    for (int i = 0; i < 16; i++) {
        int h = ll + (i << 4);
        float xn = fmaxf((v[i] - mean) * rstd * gam[h] + bet[h], 0.f);
        __nv_bfloat16 hb = __float2bfloat16(xn);
        __nv_bfloat16 lb = __float2bfloat16(xn - __bfloat162float(hb));
        xh[rr * XSTRIDE + h] = hb;
        xl[rr * XSTRIDE + h] = lb;
    }
}

__global__ void __launch_bounds__(NTHREADS, 1)
model_kernel(const float* __restrict__ s0, const float* __restrict__ prices,
             const float* __restrict__ b1, const float* __restrict__ g1,
             const float* __restrict__ be1, const float* __restrict__ b2,
             const float* __restrict__ g2, const float* __restrict__ be2,
             const float* __restrict__ bo, float* __restrict__ out) {
    extern __shared__ char smc[];
    const uint32_t sb = smem_u32(smc);
    const int tid = threadIdx.x;
    const int b0  = blockIdx.x * M_ROWS;
    float* y_sm   = (float*)(smc + SM_Y);
    float* s_s    = (float*)(smc + SM_SS);
    float* s_cost = (float*)(smc + SM_COST);
    int*   s_last = (int*)(smc + SM_LAST);

    const uint32_t XA_H = sb + SM_XA_H, XA_L = sb + SM_XA_L;
    const uint32_t XB_H = sb + SM_XB_H, XB_L = sb + SM_XB_L;

    // init s_s + XA tiles (cols 100..111 zero for k-padding)
    {
        __nv_bfloat16* ah = (__nv_bfloat16*)(smc + SM_XA_H);
        __nv_bfloat16* al = (__nv_bfloat16*)(smc + SM_XA_L);
        for (int q = tid; q < 32 * 112; q += NTHREADS) {
            int n = q / 112, c = q - n * 112;
            float sv = (c < S_DIM) ? s0[(size_t)(b0 + n) * S_DIM + c] : 0.f;
            if (c < S_DIM) s_s[n * 128 + c] = sv;
            __nv_bfloat16 hb = __float2bfloat16(sv);
            __nv_bfloat16 lb = __float2bfloat16(sv - __bfloat162float(hb));
            ah[n * XSTRIDE + c] = hb;
            al[n * XSTRIDE + c] = lb;
        }
    }
    if (tid < M_ROWS) s_cost[tid] = 0.f;
    __syncthreads();

    // prologue: prefetch units 0..2
    prefetch_unit(smc, 0, tid);
    prefetch_unit(smc, 1, tid);
    prefetch_unit(smc, 2, tid);

    const int rr = tid >> 4, ll = tid & 15;

    for (int t = 0; t < T_STEPS - 1; t++) {
        float pr[7];
        const float* prow = prices + ((size_t)(b0 + rr) * T_STEPS + t) * S_DIM;
#pragma unroll
        for (int i2 = 0; i2 < 7; i2++) {
            int idx = ll + (i2 << 4);
            pr[i2] = (idx < S_DIM) ? prow[idx] : 0.f;
        }
        const int U = t * UNITS_PER_STEP;

        // ---- L1: y = s @ W1^T  (7 ksteps, A = XA) ----
        {
            float acc[4][4];
#pragma unroll
            for (int j = 0; j < 4; j++)
#pragma unroll
                for (int i = 0; i < 4; i++) acc[j][i] = 0.f;
#pragma unroll 1
            for (int j = 0; j < 7; j++) unit4(smc, sb, tid, U + j, j, XA_H, XA_L, acc);
            store_acc4(y_sm, tid, acc);
        }
        __syncthreads();
        epi_ln(smc, tid, b1 + t * H_DIM, g1 + t * H_DIM, be1 + t * H_DIM);

        // ---- L2: y = x @ W2^T  (16 ksteps, A = XB) ----
        {
            float acc[4][4];
#pragma unroll
            for (int j = 0; j < 4; j++)
#pragma unroll
                for (int i = 0; i < 4; i++) acc[j][i] = 0.f;
#pragma unroll 1
            for (int j = 0; j < 16; j++) unit4(smc, sb, tid, U + 7 + j, j, XB_H, XB_L, acc);
            store_acc4(y_sm, tid, acc);
        }
        __syncthreads();
        epi_ln(smc, tid, b2 + t * H_DIM, g2 + t * H_DIM, be2 + t * H_DIM);

        // ---- L3: y[:,0..127] = x @ Wo^T  (16 ksteps, 128 padded rows) ----
        {
            float acc[2][4];
#pragma unroll
            for (int j = 0; j < 2; j++)
#pragma unroll
                for (int i = 0; i < 4; i++) acc[j][i] = 0.f;
#pragma unroll 1
            for (int j = 0; j < 16; j++) unit2(smc, sb, tid, U + 23 + j, j, XB_H, XB_L, acc);
            store_acc2(y_sm, tid, acc);
        }
        __syncthreads();

        // ---- elementwise: a = min(y + bo, s); cost; s -= a; rebuild XA tiles ----
        {
            const float* bo_t = bo + t * S_DIM;
            __nv_bfloat16* ah = (__nv_bfloat16*)(smc + SM_XA_H);
            __nv_bfloat16* al = (__nv_bfloat16*)(smc + SM_XA_L);
            float part = 0.f;
#pragma unroll
            for (int i2 = 0; i2 < 7; i2++) {
                int idx = ll + (i2 << 4);
                if (idx < S_DIM) {
                    float sv = s_s[rr * 128 + idx];
                    float a  = fminf(y_sm[rr * YSTRIDE + idx] + bo_t[idx], sv);
                    float pa = pr[i2] * a;
                    part += pa + 0.01f * pa * pa;
                    float ns = sv - a;
                    s_s[rr * 128 + idx] = ns;
                    __nv_bfloat16 hb = __float2bfloat16(ns);
                    __nv_bfloat16 lb = __float2bfloat16(ns - __bfloat162float(hb));
                    ah[rr * XSTRIDE + idx] = hb;
                    al[rr * XSTRIDE + idx] = lb;
                }
            }
#pragma unroll
            for (int o = 8; o >= 1; o >>= 1)
                part += __shfl_xor_sync(0xffffffffu, part, o);
            if (ll == 0) s_cost[rr] += part;
        }
        __syncthreads();
    }

    // terminal step: a = s
    {
        const float* p = prices + ((size_t)(b0 + rr) * T_STEPS + (T_STEPS - 1)) * S_DIM;
        float part = 0.f;
#pragma unroll
        for (int i2 = 0; i2 < 7; i2++) {
            int idx = ll + (i2 << 4);
            if (idx < S_DIM) {
                float sv = s_s[rr * 128 + idx];
                float pa = p[idx] * sv;
                part += pa + 0.01f * pa * pa;
            }
        }
#pragma unroll
        for (int o = 8; o >= 1; o >>= 1)
            part += __shfl_xor_sync(0xffffffffu, part, o);
        if (ll == 0) s_cost[rr] += part;
    }
    cp_wait<0>();
    __syncthreads();

    // last-CTA-done reduction
    if (tid == 0) {
        float tot = 0.f;
#pragma unroll
        for (int r = 0; r < M_ROWS; r++) tot += s_cost[r];
        g_partials[blockIdx.x] = tot;
        __threadfence();
        unsigned old = atomicAdd(&g_done, 1u);
        *s_last = (old == N_CTA - 1);
    }
    __syncthreads();
    if (*s_last) {
        float v = (tid < N_CTA) ? g_partials[tid] : 0.f;
#pragma unroll
        for (int o = 16; o >= 1; o >>= 1)
            v += __shfl_xor_sync(0xffffffffu, v, o);
        if (tid < N_CTA && (tid & 31) == 0) s_cost[tid >> 5] = v;
        __syncthreads();
        if (tid == 0) {
            out[0] = (s_cost[0] + s_cost[1] + s_cost[2] + s_cost[3]) * (1.f / (float)B_ROWS);
            g_done = 0;
        }
    }
}

extern "C" void kernel_launch(void* const* d_in, const int* in_sizes, int n_in,
                              void* d_out, int out_size) {
    const float* s0     = (const float*)d_in[0];
    const float* prices = (const float*)d_in[1];
    const float* W1     = (const float*)d_in[2];
    const float* b1     = (const float*)d_in[3];
    const float* g1     = (const float*)d_in[4];
    const float* be1    = (const float*)d_in[5];
    const float* W2     = (const float*)d_in[6];
    const float* b2     = (const float*)d_in[7];
    const float* g2     = (const float*)d_in[8];
    const float* be2    = (const float*)d_in[9];
    const float* Wo     = (const float*)d_in[10];
    const float* bo     = (const float*)d_in[11];

    prep_kernel<<<N_UNITS_TOT, 256>>>(W1, W2, Wo);
    cudaFuncSetAttribute(model_kernel, cudaFuncAttributeMaxDynamicSharedMemorySize, SM_TOTAL);
    model_kernel<<<N_CTA, NTHREADS, SM_TOTAL>>>(s0, prices, b1, g1, be1,
                                                b2, g2, be2, bo, (float*)d_out);
}

// round 16
// speedup vs baseline: 1.7779x; 1.2737x over previous
#include <cuda_runtime.h>
#include <cuda_bf16.h>
#include <cstdint>

#define T_STEPS 50
#define S_DIM   100
#define H_DIM   256
#define B_ROWS  4096
#define M_ROWS  32
#define N_CTA   128
#define NTHREADS 512
#define UNITS_PER_STEP 39            // 7 (L1) + 16 (L2) + 16 (L3)
#define N_UNITS_TOT (49 * UNITS_PER_STEP)
#define USTRIDE 16384                // unit stride in g_wbuf (bytes)
#define XSTRIDE 264                  // activation tile row stride (bf16 elems)
#define YSTRIDE 260                  // y row stride (f32 elems)

// ---- smem byte map ----
#define SM_XA_H 0                    // s tiles hi (32 x 264 bf16 = 16896)
#define SM_XA_L 16896
#define SM_XB_H 33792                // x tiles hi
#define SM_XB_L 50688
#define SM_Y    67584                // 32 x 260 f32 = 33280
#define SM_SS   100864               // 32 x 128 f32
#define SM_COST 117248
#define SM_LAST 117376
#define SM_TOTAL 117392

// Weights in per-lane MMA-fragment order:
// big unit (L1/L2): 8 n-groups(32n) * [hi: 32 lanes * 32B | lo: same] = 16KB
// small unit (L3):  8 n-groups(16n) * [hi: 32 lanes * 16B | lo: same] = 8KB
__device__ unsigned char g_wbuf[(size_t)N_UNITS_TOT * USTRIDE];
__device__ float    g_partials[N_CTA];
__device__ unsigned g_done;

// ---------------- helpers ----------------
__device__ __forceinline__ uint32_t smem_u32(const void* p) {
    uint32_t a;
    asm("{ .reg .u64 t; cvta.to.shared.u64 t, %1; cvt.u32.u64 %0, t; }" : "=r"(a) : "l"(p));
    return a;
}
__device__ __forceinline__ void split2(float f0, float f1, unsigned& h, unsigned& l) {
    asm("cvt.rn.bf16x2.f32 %0, %1, %2;" : "=r"(h) : "f"(f1), "f"(f0));
    __nv_bfloat162 hb = *reinterpret_cast<__nv_bfloat162*>(&h);
    float e0 = f0 - __bfloat162float(hb.x);
    float e1 = f1 - __bfloat162float(hb.y);
    asm("cvt.rn.bf16x2.f32 %0, %1, %2;" : "=r"(l) : "f"(e1), "f"(e0));
}
__device__ __forceinline__ void ldsm4(uint32_t* r, uint32_t a) {
    asm volatile("ldmatrix.sync.aligned.m8n8.x4.shared.b16 {%0,%1,%2,%3}, [%4];"
        : "=r"(r[0]), "=r"(r[1]), "=r"(r[2]), "=r"(r[3]) : "r"(a));
}
__device__ __forceinline__ void mma16816(float* d, const uint32_t* a, uint32_t b0, uint32_t b1) {
    asm volatile(
        "mma.sync.aligned.m16n8k16.row.col.f32.bf16.bf16.f32 "
        "{%0,%1,%2,%3}, {%4,%5,%6,%7}, {%8,%9}, {%0,%1,%2,%3};"
        : "+f"(d[0]), "+f"(d[1]), "+f"(d[2]), "+f"(d[3])
        : "r"(a[0]), "r"(a[1]), "r"(a[2]), "r"(a[3]), "r"(b0), "r"(b1));
}

// ---------------- prep: fp32 weights -> per-lane fragment-order bf16 hi/lo ----------------
// unit u = t*39 + j.  j 0..6: W1 kstep j; 7..22: W2 kstep j-7; 23..38: Wo kstep j-23.
// Fragment word w of lane l: W[n0 + 8*(w>>1) + (l>>2), kb + 8*(w&1) + 2*(l&3) + {0,1}]
__global__ void prep_kernel(const float* __restrict__ W1, const float* __restrict__ W2,
                            const float* __restrict__ Wo) {
    int u = blockIdx.x;
    int t = u / UNITS_PER_STEP, j = u % UNITS_PER_STEP;
    int g = threadIdx.x >> 5, l = threadIdx.x & 31;
    const float* src; int rstride, kbase, kmax, rmax; bool small;
    if (j < 7)       { src = W1 + (size_t)t * H_DIM * S_DIM; rstride = S_DIM; kbase = j * 16;        kmax = S_DIM; rmax = 256; small = false; }
    else if (j < 23) { src = W2 + (size_t)t * H_DIM * H_DIM; rstride = H_DIM; kbase = (j - 7) * 16;  kmax = H_DIM; rmax = 256; small = false; }
    else             { src = Wo + (size_t)t * S_DIM * H_DIM; rstride = H_DIM; kbase = (j - 23) * 16; kmax = H_DIM; rmax = 100; small = true; }
    unsigned char* dst = g_wbuf + (size_t)u * USTRIDE;
    int n0 = small ? (g << 4) : (g << 5);
    int nw = small ? 4 : 8;
    unsigned hi[8], lo[8];
#pragma unroll
    for (int w = 0; w < 8; w++) {
        if (w < nw) {
            int n = n0 + ((w >> 1) << 3) + (l >> 2);
            int k = kbase + ((w & 1) << 3) + ((l & 3) << 1);
            float f0 = (n < rmax && k < kmax)     ? src[(size_t)n * rstride + k]     : 0.f;
            float f1 = (n < rmax && k + 1 < kmax) ? src[(size_t)n * rstride + k + 1] : 0.f;
            split2(f0, f1, hi[w], lo[w]);
        } else { hi[w] = 0; lo[w] = 0; }
    }
    if (small) {
        *(uint4*)(dst + (g << 10) + (l << 4))       = make_uint4(hi[0], hi[1], hi[2], hi[3]);
        *(uint4*)(dst + (g << 10) + 512 + (l << 4)) = make_uint4(lo[0], lo[1], lo[2], lo[3]);
    } else {
        *(uint4*)(dst + (g << 11) + (l << 5))        = make_uint4(hi[0], hi[1], hi[2], hi[3]);
        *(uint4*)(dst + (g << 11) + (l << 5) + 16)   = make_uint4(hi[4], hi[5], hi[6], hi[7]);
        *(uint4*)(dst + (g << 11) + 1024 + (l << 5))      = make_uint4(lo[0], lo[1], lo[2], lo[3]);
        *(uint4*)(dst + (g << 11) + 1024 + (l << 5) + 16) = make_uint4(lo[4], lo[5], lo[6], lo[7]);
    }
}

// ---------------- big-layer GEMM: KS ksteps, A from smem tiles, B via LDG ----------------
// warp w: mg=w&1 (16 m-rows), ng=w>>1 (32 n-cols). acc[4][4] over 4 n8 tiles.
template<int KS>
__device__ __forceinline__ void gemm_big(const char* wu0, uint32_t xh, uint32_t xl,
                                         int w, int l, float acc[4][4]) {
    const int mg = w & 1, ng = w >> 1;
    const char* bp = wu0 + (ng << 11) + (l << 5);
    uint32_t xo = (uint32_t)(((mg << 4) + (l & 15)) * XSTRIDE + ((l >> 4) << 3)) * 2;
    uint4 h0 = *(const uint4*)bp;
    uint4 h1 = *(const uint4*)(bp + 16);
    uint4 l0 = *(const uint4*)(bp + 1024);
    uint4 l1 = *(const uint4*)(bp + 1040);
#pragma unroll 1
    for (int j = 0; j < KS; j++) {
        uint4 nh0, nh1, nl0, nl1;
        if (j + 1 < KS) {
            const char* np = bp + (j + 1) * USTRIDE;
            nh0 = *(const uint4*)np;
            nh1 = *(const uint4*)(np + 16);
            nl0 = *(const uint4*)(np + 1024);
            nl1 = *(const uint4*)(np + 1040);
        }
        uint32_t ah[4], al[4];
        ldsm4(ah, xh + xo);
        ldsm4(al, xl + xo);
        xo += 32;
        mma16816(acc[0], ah, h0.x, h0.y);
        mma16816(acc[1], ah, h0.z, h0.w);
        mma16816(acc[2], ah, h1.x, h1.y);
        mma16816(acc[3], ah, h1.z, h1.w);
        mma16816(acc[0], ah, l0.x, l0.y);
        mma16816(acc[1], ah, l0.z, l0.w);
        mma16816(acc[2], ah, l1.x, l1.y);
        mma16816(acc[3], ah, l1.z, l1.w);
        mma16816(acc[0], al, h0.x, h0.y);
        mma16816(acc[1], al, h0.z, h0.w);
        mma16816(acc[2], al, h1.x, h1.y);
        mma16816(acc[3], al, h1.z, h1.w);
        h0 = nh0; h1 = nh1; l0 = nl0; l1 = nl1;
    }
}

// ---------------- L3 GEMM: 16 ksteps, 100(->128) output cols ----------------
// warp w: mg=w&1, ng=w>>1 (16 n-cols). acc[2][4].
__device__ __forceinline__ void gemm_small(const char* wu0, uint32_t xh, uint32_t xl,
                                           int w, int l, float acc[2][4]) {
    const int mg = w & 1, ng = w >> 1;
    const char* bp = wu0 + (ng << 10) + (l << 4);
    uint32_t xo = (uint32_t)(((mg << 4) + (l & 15)) * XSTRIDE + ((l >> 4) << 3)) * 2;
    uint4 h0 = *(const uint4*)bp;
    uint4 l0 = *(const uint4*)(bp + 512);
#pragma unroll 1
    for (int j = 0; j < 16; j++) {
        uint4 nh0, nl0;
        if (j + 1 < 16) {
            const char* np = bp + (j + 1) * USTRIDE;
            nh0 = *(const uint4*)np;
            nl0 = *(const uint4*)(np + 512);
        }
        uint32_t ah[4], al[4];
        ldsm4(ah, xh + xo);
        ldsm4(al, xl + xo);
        xo += 32;
        mma16816(acc[0], ah, h0.x, h0.y);
        mma16816(acc[1], ah, h0.z, h0.w);
        mma16816(acc[0], ah, l0.x, l0.y);
        mma16816(acc[1], ah, l0.z, l0.w);
        mma16816(acc[0], al, h0.x, h0.y);
        mma16816(acc[1], al, h0.z, h0.w);
        h0 = nh0; l0 = nl0;
    }
}

__device__ __forceinline__ void store_acc4(float* y, int w, int l, float acc[4][4]) {
    int m = ((w & 1) << 4) + (l >> 2);
    int n0 = (w >> 1) << 5;
    int c = (l & 3) << 1;
#pragma unroll
    for (int i = 0; i < 4; i++) {
        int n = n0 + (i << 3) + c;
        y[m * YSTRIDE + n] = acc[i][0];       y[m * YSTRIDE + n + 1] = acc[i][1];
        y[(m + 8) * YSTRIDE + n] = acc[i][2]; y[(m + 8) * YSTRIDE + n + 1] = acc[i][3];
    }
}
__device__ __forceinline__ void store_acc2(float* y, int w, int l, float acc[2][4]) {
    int m = ((w & 1) << 4) + (l >> 2);
    int n0 = (w >> 1) << 4;
    int c = (l & 3) << 1;
#pragma unroll
    for (int i = 0; i < 2; i++) {
        int n = n0 + (i << 3) + c;
        y[m * YSTRIDE + n] = acc[i][0];       y[m * YSTRIDE + n + 1] = acc[i][1];
        y[(m + 8) * YSTRIDE + n] = acc[i][2]; y[(m + 8) * YSTRIDE + n + 1] = acc[i][3];
    }
}

// LN + relu from y (fp32) -> XB bf16 hi/lo tiles
__device__ __forceinline__ void epi_ln(char* smc, int tid,
                                       const float* __restrict__ bias,
                                       const float* __restrict__ gam,
                                       const float* __restrict__ bet) {
    float* y = (float*)(smc + SM_Y);
    int rr = tid >> 4, ll = tid & 15;
    float v[16], sum = 0.f, sq = 0.f;
#pragma unroll
    for (int i = 0; i < 16; i++) {
        int h = ll + (i << 4);
        float tv = y[rr * YSTRIDE + h] + bias[h];
        v[i] = tv; sum += tv; sq = fmaf(tv, tv, sq);
    }
#pragma unroll
    for (int o = 8; o >= 1; o >>= 1) {
        sum += __shfl_xor_sync(0xffffffffu, sum, o);
        sq  += __shfl_xor_sync(0xffffffffu, sq, o);
    }
    float mean = sum * (1.f / 256.f);
    float var  = sq * (1.f / 256.f) - mean * mean;
    float rstd = rsqrtf(var + 1e-5f);
    __nv_bfloat16* xh = (__nv_bfloat16*)(smc + SM_XB_H);
    __nv_bfloat16* xl = (__nv_bfloat16*)(smc + SM_XB_L);
#pragma unroll
    for (int i = 0; i < 16; i++) {
        int h = ll + (i << 4);
        float xn = fmaxf((v[i] - mean) * rstd * gam[h] + bet[h], 0.f);
        __nv_bfloat16 hb = __float2bfloat16(xn);
        __nv_bfloat16 lb = __float2bfloat16(xn - __bfloat162float(hb));
        xh[rr * XSTRIDE + h] = hb;
        xl[rr * XSTRIDE + h] = lb;
    }
}

__global__ void __launch_bounds__(NTHREADS, 1)
model_kernel(const float* __restrict__ s0, const float* __restrict__ prices,
             const float* __restrict__ b1, const float* __restrict__ g1,
             const float* __restrict__ be1, const float* __restrict__ b2,
             const float* __restrict__ g2, const float* __restrict__ be2,
             const float* __restrict__ bo, float* __restrict__ out) {
    extern __shared__ char smc[];
    const uint32_t sb = smem_u32(smc);
    const int tid = threadIdx.x;
    const int w = tid >> 5, l = tid & 31;
    const int b0  = blockIdx.x * M_ROWS;
    float* y_sm   = (float*)(smc + SM_Y);
    float* s_s    = (float*)(smc + SM_SS);
    float* s_cost = (float*)(smc + SM_COST);
    int*   s_last = (int*)(smc + SM_LAST);

    const uint32_t XA_H = sb + SM_XA_H, XA_L = sb + SM_XA_L;
    const uint32_t XB_H = sb + SM_XB_H, XB_L = sb + SM_XB_L;

    // init s_s + XA tiles (cols 100..111 zero for k-padding)
    {
        __nv_bfloat16* ah = (__nv_bfloat16*)(smc + SM_XA_H);
        __nv_bfloat16* al = (__nv_bfloat16*)(smc + SM_XA_L);
        for (int q = tid; q < 32 * 112; q += NTHREADS) {
            int n = q / 112, c = q - n * 112;
            float sv = (c < S_DIM) ? s0[(size_t)(b0 + n) * S_DIM + c] : 0.f;
            if (c < S_DIM) s_s[n * 128 + c] = sv;
            __nv_bfloat16 hb = __float2bfloat16(sv);
            __nv_bfloat16 lb = __float2bfloat16(sv - __bfloat162float(hb));
            ah[n * XSTRIDE + c] = hb;
            al[n * XSTRIDE + c] = lb;
        }
    }
    if (tid < M_ROWS) s_cost[tid] = 0.f;
    __syncthreads();

    const int rr = tid >> 4, ll = tid & 15;

    for (int t = 0; t < T_STEPS - 1; t++) {
        float pr[7];
        const float* prow = prices + ((size_t)(b0 + rr) * T_STEPS + t) * S_DIM;
#pragma unroll
        for (int i2 = 0; i2 < 7; i2++) {
            int idx = ll + (i2 << 4);
            pr[i2] = (idx < S_DIM) ? prow[idx] : 0.f;
        }
        const char* ub = (const char*)g_wbuf + (size_t)(t * UNITS_PER_STEP) * USTRIDE;

        // ---- L1: y = s @ W1^T (7 ksteps) ----
        {
            float acc[4][4];
#pragma unroll
            for (int j = 0; j < 4; j++)
#pragma unroll
                for (int i = 0; i < 4; i++) acc[j][i] = 0.f;
            gemm_big<7>(ub, XA_H, XA_L, w, l, acc);
            store_acc4(y_sm, w, l, acc);
        }
        __syncthreads();
        epi_ln(smc, tid, b1 + t * H_DIM, g1 + t * H_DIM, be1 + t * H_DIM);
        __syncthreads();

        // ---- L2: y = x @ W2^T (16 ksteps) ----
        {
            float acc[4][4];
#pragma unroll
            for (int j = 0; j < 4; j++)
#pragma unroll
                for (int i = 0; i < 4; i++) acc[j][i] = 0.f;
            gemm_big<16>(ub + 7 * USTRIDE, XB_H, XB_L, w, l, acc);
            store_acc4(y_sm, w, l, acc);
        }
        __syncthreads();
        epi_ln(smc, tid, b2 + t * H_DIM, g2 + t * H_DIM, be2 + t * H_DIM);
        __syncthreads();

        // ---- L3: y[:,0..127] = x @ Wo^T (16 ksteps) ----
        {
            float acc[2][4];
#pragma unroll
            for (int j = 0; j < 2; j++)
#pragma unroll
                for (int i = 0; i < 4; i++) acc[j][i] = 0.f;
            gemm_small(ub + 23 * USTRIDE, XB_H, XB_L, w, l, acc);
            store_acc2(y_sm, w, l, acc);
        }
        __syncthreads();

        // ---- elementwise: a = min(y + bo, s); cost; s -= a; rebuild XA tiles ----
        {
            const float* bo_t = bo + t * S_DIM;
            __nv_bfloat16* ah = (__nv_bfloat16*)(smc + SM_XA_H);
            __nv_bfloat16* al = (__nv_bfloat16*)(smc + SM_XA_L);
            float part = 0.f;
#pragma unroll
            for (int i2 = 0; i2 < 7; i2++) {
                int idx = ll + (i2 << 4);
                if (idx < S_DIM) {
                    float sv = s_s[rr * 128 + idx];
                    float a  = fminf(y_sm[rr * YSTRIDE + idx] + bo_t[idx], sv);
                    float pa = pr[i2] * a;
                    part += pa + 0.01f * pa * pa;
                    float ns = sv - a;
                    s_s[rr * 128 + idx] = ns;
                    __nv_bfloat16 hb = __float2bfloat16(ns);
                    __nv_bfloat16 lb = __float2bfloat16(ns - __bfloat162float(hb));
                    ah[rr * XSTRIDE + idx] = hb;
                    al[rr * XSTRIDE + idx] = lb;
                }
            }
#pragma unroll
            for (int o = 8; o >= 1; o >>= 1)
                part += __shfl_xor_sync(0xffffffffu, part, o);
            if (ll == 0) s_cost[rr] += part;
        }
        __syncthreads();
    }

    // terminal step: a = s
    {
        const float* p = prices + ((size_t)(b0 + rr) * T_STEPS + (T_STEPS - 1)) * S_DIM;
        float part = 0.f;
#pragma unroll
        for (int i2 = 0; i2 < 7; i2++) {
            int idx = ll + (i2 << 4);
            if (idx < S_DIM) {
                float sv = s_s[rr * 128 + idx];
                float pa = p[idx] * sv;
                part += pa + 0.01f * pa * pa;
            }
        }
#pragma unroll
        for (int o = 8; o >= 1; o >>= 1)
            part += __shfl_xor_sync(0xffffffffu, part, o);
        if (ll == 0) s_cost[rr] += part;
    }
    __syncthreads();

    // last-CTA-done reduction
    if (tid == 0) {
        float tot = 0.f;
#pragma unroll
        for (int r = 0; r < M_ROWS; r++) tot += s_cost[r];
        g_partials[blockIdx.x] = tot;
        __threadfence();
        unsigned old = atomicAdd(&g_done, 1u);
        *s_last = (old == N_CTA - 1);
    }
    __syncthreads();
    if (*s_last) {
        float v = (tid < N_CTA) ? g_partials[tid] : 0.f;
#pragma unroll
        for (int o = 16; o >= 1; o >>= 1)
            v += __shfl_xor_sync(0xffffffffu, v, o);
        if (tid < N_CTA && (tid & 31) == 0) s_cost[tid >> 5] = v;
        __syncthreads();
        if (tid == 0) {
            out[0] = (s_cost[0] + s_cost[1] + s_cost[2] + s_cost[3]) * (1.f / (float)B_ROWS);
            g_done = 0;
        }
    }
}

extern "C" void kernel_launch(void* const* d_in, const int* in_sizes, int n_in,
                              void* d_out, int out_size) {
    const float* s0     = (const float*)d_in[0];
    const float* prices = (const float*)d_in[1];
    const float* W1     = (const float*)d_in[2];
    const float* b1     = (const float*)d_in[3];
    const float* g1     = (const float*)d_in[4];
    const float* be1    = (const float*)d_in[5];
    const float* W2     = (const float*)d_in[6];
    const float* b2     = (const float*)d_in[7];
    const float* g2     = (const float*)d_in[8];
    const float* be2    = (const float*)d_in[9];
    const float* Wo     = (const float*)d_in[10];
    const float* bo     = (const float*)d_in[11];

    prep_kernel<<<N_UNITS_TOT, 256>>>(W1, W2, Wo);
    cudaFuncSetAttribute(model_kernel, cudaFuncAttributeMaxDynamicSharedMemorySize, SM_TOTAL);
    model_kernel<<<N_CTA, NTHREADS, SM_TOTAL>>>(s0, prices, b1, g1, be1,
                                                b2, g2, be2, bo, (float*)d_out);
}

// round 17
// speedup vs baseline: 2.0954x; 1.1786x over previous
#include <cuda_runtime.h>
#include <cuda_bf16.h>
#include <cstdint>

#define T_STEPS 50
#define S_DIM   100
#define H_DIM   256
#define B_ROWS  4096
#define M_ROWS  16
#define N_CTA   256
#define NTHREADS 256
#define UNITS_PER_STEP 39            // 7 (L1) + 16 (L2) + 16 (L3)
#define N_UNITS_TOT (49 * UNITS_PER_STEP)
#define USTRIDE 16384                // unit stride in g_wbuf (bytes)
#define XSTRIDE 264                  // activation tile row stride (bf16 elems)
#define YSTRIDE 260                  // y row stride (f32 elems)

// ---- smem byte map (per CTA) ----
#define SM_XA_H 0                    // s tiles hi (16 x 264 bf16 = 8448)
#define SM_XA_L 8448
#define SM_XB_H 16896                // x tiles hi
#define SM_XB_L 25344
#define SM_Y    33792                // 16 x 260 f32 = 16640
#define SM_SS   50432                // 16 x 128 f32
#define SM_COST 58624                // 16 floats + 8 scratch
#define SM_LAST 58752
#define SM_TOTAL 58768

// Weights in per-lane MMA-fragment order:
// big unit (L1/L2): 8 n-groups(32n) * [hi: 32 lanes * 32B | lo: same] = 16KB
// small unit (L3):  8 n-groups(16n) * [hi: 32 lanes * 16B | lo: same] = 8KB
__device__ unsigned char g_wbuf[(size_t)N_UNITS_TOT * USTRIDE];
__device__ float    g_partials[N_CTA];
__device__ unsigned g_done;

// ---------------- helpers ----------------
__device__ __forceinline__ uint32_t smem_u32(const void* p) {
    uint32_t a;
    asm("{ .reg .u64 t; cvta.to.shared.u64 t, %1; cvt.u32.u64 %0, t; }" : "=r"(a) : "l"(p));
    return a;
}
__device__ __forceinline__ void split2(float f0, float f1, unsigned& h, unsigned& l) {
    asm("cvt.rn.bf16x2.f32 %0, %1, %2;" : "=r"(h) : "f"(f1), "f"(f0));
    __nv_bfloat162 hb = *reinterpret_cast<__nv_bfloat162*>(&h);
    float e0 = f0 - __bfloat162float(hb.x);
    float e1 = f1 - __bfloat162float(hb.y);
    asm("cvt.rn.bf16x2.f32 %0, %1, %2;" : "=r"(l) : "f"(e1), "f"(e0));
}
__device__ __forceinline__ void ldsm4(uint32_t* r, uint32_t a) {
    asm volatile("ldmatrix.sync.aligned.m8n8.x4.shared.b16 {%0,%1,%2,%3}, [%4];"
        : "=r"(r[0]), "=r"(r[1]), "=r"(r[2]), "=r"(r[3]) : "r"(a));
}
__device__ __forceinline__ void mma16816(float* d, const uint32_t* a, uint32_t b0, uint32_t b1) {
    asm volatile(
        "mma.sync.aligned.m16n8k16.row.col.f32.bf16.bf16.f32 "
        "{%0,%1,%2,%3}, {%4,%5,%6,%7}, {%8,%9}, {%0,%1,%2,%3};"
        : "+f"(d[0]), "+f"(d[1]), "+f"(d[2]), "+f"(d[3])
        : "r"(a[0]), "r"(a[1]), "r"(a[2]), "r"(a[3]), "r"(b0), "r"(b1));
}

// ---------------- prep: fp32 weights -> per-lane fragment-order bf16 hi/lo ----------------
// unit u = t*39 + j.  j 0..6: W1 kstep j; 7..22: W2 kstep j-7; 23..38: Wo kstep j-23.
// Fragment word w of lane l: W[n0 + 8*(w>>1) + (l>>2), kb + 8*(w&1) + 2*(l&3) + {0,1}]
__global__ void prep_kernel(const float* __restrict__ W1, const float* __restrict__ W2,
                            const float* __restrict__ Wo) {
    int u = blockIdx.x;
    int t = u / UNITS_PER_STEP, j = u % UNITS_PER_STEP;
    int g = threadIdx.x >> 5, l = threadIdx.x & 31;
    const float* src; int rstride, kbase, kmax, rmax; bool small;
    if (j < 7)       { src = W1 + (size_t)t * H_DIM * S_DIM; rstride = S_DIM; kbase = j * 16;        kmax = S_DIM; rmax = 256; small = false; }
    else if (j < 23) { src = W2 + (size_t)t * H_DIM * H_DIM; rstride = H_DIM; kbase = (j - 7) * 16;  kmax = H_DIM; rmax = 256; small = false; }
    else             { src = Wo + (size_t)t * S_DIM * H_DIM; rstride = H_DIM; kbase = (j - 23) * 16; kmax = H_DIM; rmax = 100; small = true; }
    unsigned char* dst = g_wbuf + (size_t)u * USTRIDE;
    int n0 = small ? (g << 4) : (g << 5);
    int nw = small ? 4 : 8;
    unsigned hi[8], lo[8];
#pragma unroll
    for (int w = 0; w < 8; w++) {
        if (w < nw) {
            int n = n0 + ((w >> 1) << 3) + (l >> 2);
            int k = kbase + ((w & 1) << 3) + ((l & 3) << 1);
            float f0 = (n < rmax && k < kmax)     ? src[(size_t)n * rstride + k]     : 0.f;
            float f1 = (n < rmax && k + 1 < kmax) ? src[(size_t)n * rstride + k + 1] : 0.f;
            split2(f0, f1, hi[w], lo[w]);
        } else { hi[w] = 0; lo[w] = 0; }
    }
    if (small) {
        *(uint4*)(dst + (g << 10) + (l << 4))       = make_uint4(hi[0], hi[1], hi[2], hi[3]);
        *(uint4*)(dst + (g << 10) + 512 + (l << 4)) = make_uint4(lo[0], lo[1], lo[2], lo[3]);
    } else {
        *(uint4*)(dst + (g << 11) + (l << 5))        = make_uint4(hi[0], hi[1], hi[2], hi[3]);
        *(uint4*)(dst + (g << 11) + (l << 5) + 16)   = make_uint4(hi[4], hi[5], hi[6], hi[7]);
        *(uint4*)(dst + (g << 11) + 1024 + (l << 5))      = make_uint4(lo[0], lo[1], lo[2], lo[3]);
        *(uint4*)(dst + (g << 11) + 1024 + (l << 5) + 16) = make_uint4(lo[4], lo[5], lo[6], lo[7]);
    }
}

// ---------------- big-layer GEMM: KS ksteps, A (16 rows) from smem, B via LDG ----------------
// warp w owns n-group w (32 n-cols): no duplicate weight loads across warps.
template<int KS>
__device__ __forceinline__ void gemm_big(const char* wu0, uint32_t xh, uint32_t xl,
                                         int w, int l, float acc[4][4]) {
    const char* bp = wu0 + (w << 11) + (l << 5);
    uint32_t xo = (uint32_t)((l & 15) * XSTRIDE + ((l >> 4) << 3)) * 2;
    uint4 h0 = *(const uint4*)bp;
    uint4 h1 = *(const uint4*)(bp + 16);
    uint4 l0 = *(const uint4*)(bp + 1024);
    uint4 l1 = *(const uint4*)(bp + 1040);
#pragma unroll 1
    for (int j = 0; j < KS; j++) {
        uint4 nh0, nh1, nl0, nl1;
        if (j + 1 < KS) {
            const char* np = bp + (j + 1) * USTRIDE;
            nh0 = *(const uint4*)np;
            nh1 = *(const uint4*)(np + 16);
            nl0 = *(const uint4*)(np + 1024);
            nl1 = *(const uint4*)(np + 1040);
        }
        uint32_t ah[4], al[4];
        ldsm4(ah, xh + xo);
        ldsm4(al, xl + xo);
        xo += 32;
        mma16816(acc[0], ah, h0.x, h0.y);
        mma16816(acc[1], ah, h0.z, h0.w);
        mma16816(acc[2], ah, h1.x, h1.y);
        mma16816(acc[3], ah, h1.z, h1.w);
        mma16816(acc[0], ah, l0.x, l0.y);
        mma16816(acc[1], ah, l0.z, l0.w);
        mma16816(acc[2], ah, l1.x, l1.y);
        mma16816(acc[3], ah, l1.z, l1.w);
        mma16816(acc[0], al, h0.x, h0.y);
        mma16816(acc[1], al, h0.z, h0.w);
        mma16816(acc[2], al, h1.x, h1.y);
        mma16816(acc[3], al, h1.z, h1.w);
        h0 = nh0; h1 = nh1; l0 = nl0; l1 = nl1;
    }
}

// ---------------- L3 GEMM: 16 ksteps, warp w owns 16 n-cols ----------------
__device__ __forceinline__ void gemm_small(const char* wu0, uint32_t xh, uint32_t xl,
                                           int w, int l, float acc[2][4]) {
    const char* bp = wu0 + (w << 10) + (l << 4);
    uint32_t xo = (uint32_t)((l & 15) * XSTRIDE + ((l >> 4) << 3)) * 2;
    uint4 h0 = *(const uint4*)bp;
    uint4 l0 = *(const uint4*)(bp + 512);
#pragma unroll 1
    for (int j = 0; j < 16; j++) {
        uint4 nh0, nl0;
        if (j + 1 < 16) {
            const char* np = bp + (j + 1) * USTRIDE;
            nh0 = *(const uint4*)np;
            nl0 = *(const uint4*)(np + 512);
        }
        uint32_t ah[4], al[4];
        ldsm4(ah, xh + xo);
        ldsm4(al, xl + xo);
        xo += 32;
        mma16816(acc[0], ah, h0.x, h0.y);
        mma16816(acc[1], ah, h0.z, h0.w);
        mma16816(acc[0], ah, l0.x, l0.y);
        mma16816(acc[1], ah, l0.z, l0.w);
        mma16816(acc[0], al, h0.x, h0.y);
        mma16816(acc[1], al, h0.z, h0.w);
        h0 = nh0; l0 = nl0;
    }
}

__device__ __forceinline__ void store_acc4(float* y, int w, int l, float acc[4][4]) {
    int m = l >> 2;
    int n0 = w << 5;
    int c = (l & 3) << 1;
#pragma unroll
    for (int i = 0; i < 4; i++) {
        int n = n0 + (i << 3) + c;
        y[m * YSTRIDE + n] = acc[i][0];       y[m * YSTRIDE + n + 1] = acc[i][1];
        y[(m + 8) * YSTRIDE + n] = acc[i][2]; y[(m + 8) * YSTRIDE + n + 1] = acc[i][3];
    }
}
__device__ __forceinline__ void store_acc2(float* y, int w, int l, float acc[2][4]) {
    int m = l >> 2;
    int n0 = w << 4;
    int c = (l & 3) << 1;
#pragma unroll
    for (int i = 0; i < 2; i++) {
        int n = n0 + (i << 3) + c;
        y[m * YSTRIDE + n] = acc[i][0];       y[m * YSTRIDE + n + 1] = acc[i][1];
        y[(m + 8) * YSTRIDE + n] = acc[i][2]; y[(m + 8) * YSTRIDE + n + 1] = acc[i][3];
    }
}

// LN + relu from y (fp32) -> XB bf16 hi/lo tiles (16 rows, 16 lanes/row)
__device__ __forceinline__ void epi_ln(char* smc, int tid,
                                       const float* __restrict__ bias,
                                       const float* __restrict__ gam,
                                       const float* __restrict__ bet) {
    float* y = (float*)(smc + SM_Y);
    int rr = tid >> 4, ll = tid & 15;
    float v[16], sum = 0.f, sq = 0.f;
#pragma unroll
    for (int i = 0; i < 16; i++) {
        int h = ll + (i << 4);
        float tv = y[rr * YSTRIDE + h] + bias[h];
        v[i] = tv; sum += tv; sq = fmaf(tv, tv, sq);
    }
#pragma unroll
    for (int o = 8; o >= 1; o >>= 1) {
        sum += __shfl_xor_sync(0xffffffffu, sum, o);
        sq  += __shfl_xor_sync(0xffffffffu, sq, o);
    }
    float mean = sum * (1.f / 256.f);
    float var  = sq * (1.f / 256.f) - mean * mean;
    float rstd = rsqrtf(var + 1e-5f);
    __nv_bfloat16* xh = (__nv_bfloat16*)(smc + SM_XB_H);
    __nv_bfloat16* xl = (__nv_bfloat16*)(smc + SM_XB_L);
#pragma unroll
    for (int i = 0; i < 16; i++) {
        int h = ll + (i << 4);
        float xn = fmaxf((v[i] - mean) * rstd * gam[h] + bet[h], 0.f);
        __nv_bfloat16 hb = __float2bfloat16(xn);
        __nv_bfloat16 lb = __float2bfloat16(xn - __bfloat162float(hb));
        xh[rr * XSTRIDE + h] = hb;
        xl[rr * XSTRIDE + h] = lb;
    }
}

__global__ void __launch_bounds__(NTHREADS, 2)
model_kernel(const float* __restrict__ s0, const float* __restrict__ prices,
             const float* __restrict__ b1, const float* __restrict__ g1,
             const float* __restrict__ be1, const float* __restrict__ b2,
             const float* __restrict__ g2, const float* __restrict__ be2,
             const float* __restrict__ bo, float* __restrict__ out) {
    extern __shared__ char smc[];
    const uint32_t sb = smem_u32(smc);
    const int tid = threadIdx.x;
    const int w = tid >> 5, l = tid & 31;
    const int b0  = blockIdx.x * M_ROWS;
    float* y_sm   = (float*)(smc + SM_Y);
    float* s_s    = (float*)(smc + SM_SS);
    float* s_cost = (float*)(smc + SM_COST);
    int*   s_last = (int*)(smc + SM_LAST);

    const uint32_t XA_H = sb + SM_XA_H, XA_L = sb + SM_XA_L;
    const uint32_t XB_H = sb + SM_XB_H, XB_L = sb + SM_XB_L;

    // init s_s + XA tiles (cols 100..111 zero for k-padding)
    {
        __nv_bfloat16* ah = (__nv_bfloat16*)(smc + SM_XA_H);
        __nv_bfloat16* al = (__nv_bfloat16*)(smc + SM_XA_L);
        for (int q = tid; q < M_ROWS * 112; q += NTHREADS) {
            int n = q / 112, c = q - n * 112;
            float sv = (c < S_DIM) ? s0[(size_t)(b0 + n) * S_DIM + c] : 0.f;
            if (c < S_DIM) s_s[n * 128 + c] = sv;
            __nv_bfloat16 hb = __float2bfloat16(sv);
            __nv_bfloat16 lb = __float2bfloat16(sv - __bfloat162float(hb));
            ah[n * XSTRIDE + c] = hb;
            al[n * XSTRIDE + c] = lb;
        }
    }
    if (tid < M_ROWS) s_cost[tid] = 0.f;
    __syncthreads();

    const int rr = tid >> 4, ll = tid & 15;

    for (int t = 0; t < T_STEPS - 1; t++) {
        float pr[7];
        const float* prow = prices + ((size_t)(b0 + rr) * T_STEPS + t) * S_DIM;
#pragma unroll
        for (int i2 = 0; i2 < 7; i2++) {
            int idx = ll + (i2 << 4);
            pr[i2] = (idx < S_DIM) ? prow[idx] : 0.f;
        }
        const char* ub = (const char*)g_wbuf + (size_t)(t * UNITS_PER_STEP) * USTRIDE;

        // ---- L1: y = s @ W1^T (7 ksteps) ----
        {
            float acc[4][4];
#pragma unroll
            for (int j = 0; j < 4; j++)
#pragma unroll
                for (int i = 0; i < 4; i++) acc[j][i] = 0.f;
            gemm_big<7>(ub, XA_H, XA_L, w, l, acc);
            store_acc4(y_sm, w, l, acc);
        }
        __syncthreads();
        epi_ln(smc, tid, b1 + t * H_DIM, g1 + t * H_DIM, be1 + t * H_DIM);
        __syncthreads();

        // ---- L2: y = x @ W2^T (16 ksteps) ----
        {
            float acc[4][4];
#pragma unroll
            for (int j = 0; j < 4; j++)
#pragma unroll
                for (int i = 0; i < 4; i++) acc[j][i] = 0.f;
            gemm_big<16>(ub + 7 * USTRIDE, XB_H, XB_L, w, l, acc);
            store_acc4(y_sm, w, l, acc);
        }
        __syncthreads();
        epi_ln(smc, tid, b2 + t * H_DIM, g2 + t * H_DIM, be2 + t * H_DIM);
        __syncthreads();

        // ---- L3: y[:,0..127] = x @ Wo^T (16 ksteps) ----
        {
            float acc[2][4];
#pragma unroll
            for (int j = 0; j < 2; j++)
#pragma unroll
                for (int i = 0; i < 4; i++) acc[j][i] = 0.f;
            gemm_small(ub + 23 * USTRIDE, XB_H, XB_L, w, l, acc);
            store_acc2(y_sm, w, l, acc);
        }
        __syncthreads();

        // ---- elementwise: a = min(y + bo, s); cost; s -= a; rebuild XA tiles ----
        {
            const float* bo_t = bo + t * S_DIM;
            __nv_bfloat16* ah = (__nv_bfloat16*)(smc + SM_XA_H);
            __nv_bfloat16* al = (__nv_bfloat16*)(smc + SM_XA_L);
            float part = 0.f;
#pragma unroll
            for (int i2 = 0; i2 < 7; i2++) {
                int idx = ll + (i2 << 4);
                if (idx < S_DIM) {
                    float sv = s_s[rr * 128 + idx];
                    float a  = fminf(y_sm[rr * YSTRIDE + idx] + bo_t[idx], sv);
                    float pa = pr[i2] * a;
                    part += pa + 0.01f * pa * pa;
                    float ns = sv - a;
                    s_s[rr * 128 + idx] = ns;
                    __nv_bfloat16 hb = __float2bfloat16(ns);
                    __nv_bfloat16 lb = __float2bfloat16(ns - __bfloat162float(hb));
                    ah[rr * XSTRIDE + idx] = hb;
                    al[rr * XSTRIDE + idx] = lb;
                }
            }
#pragma unroll
            for (int o = 8; o >= 1; o >>= 1)
                part += __shfl_xor_sync(0xffffffffu, part, o);
            if (ll == 0) s_cost[rr] += part;
        }
        __syncthreads();
    }

    // terminal step: a = s
    {
        const float* p = prices + ((size_t)(b0 + rr) * T_STEPS + (T_STEPS - 1)) * S_DIM;
        float part = 0.f;
#pragma unroll
        for (int i2 = 0; i2 < 7; i2++) {
            int idx = ll + (i2 << 4);
            if (idx < S_DIM) {
                float sv = s_s[rr * 128 + idx];
                float pa = p[idx] * sv;
                part += pa + 0.01f * pa * pa;
            }
        }
#pragma unroll
        for (int o = 8; o >= 1; o >>= 1)
            part += __shfl_xor_sync(0xffffffffu, part, o);
        if (ll == 0) s_cost[rr] += part;
    }
    __syncthreads();

    // last-CTA-done reduction
    if (tid == 0) {
        float tot = 0.f;
#pragma unroll
        for (int r = 0; r < M_ROWS; r++) tot += s_cost[r];
        g_partials[blockIdx.x] = tot;
        __threadfence();
        unsigned old = atomicAdd(&g_done, 1u);
        *s_last = (old == N_CTA - 1);
    }
    __syncthreads();
    if (*s_last) {
        float v = g_partials[tid];   // NTHREADS == N_CTA == 256
#pragma unroll
        for (int o = 16; o >= 1; o >>= 1)
            v += __shfl_xor_sync(0xffffffffu, v, o);
        if ((tid & 31) == 0) s_cost[tid >> 5] = v;
        __syncthreads();
        if (tid == 0) {
            float tot = 0.f;
#pragma unroll
            for (int i = 0; i < 8; i++) tot += s_cost[i];
            out[0] = tot * (1.f / (float)B_ROWS);
            g_done = 0;
        }
    }
}

extern "C" void kernel_launch(void* const* d_in, const int* in_sizes, int n_in,
                              void* d_out, int out_size) {
    const float* s0     = (const float*)d_in[0];
    const float* prices = (const float*)d_in[1];
    const float* W1     = (const float*)d_in[2];
    const float* b1     = (const float*)d_in[3];
    const float* g1     = (const float*)d_in[4];
    const float* be1    = (const float*)d_in[5];
    const float* W2     = (const float*)d_in[6];
    const float* b2     = (const float*)d_in[7];
    const float* g2     = (const float*)d_in[8];
    const float* be2    = (const float*)d_in[9];
    const float* Wo     = (const float*)d_in[10];
    const float* bo     = (const float*)d_in[11];

    prep_kernel<<<N_UNITS_TOT, 256>>>(W1, W2, Wo);
    cudaFuncSetAttribute(model_kernel, cudaFuncAttributeMaxDynamicSharedMemorySize, SM_TOTAL);
    model_kernel<<<N_CTA, NTHREADS, SM_TOTAL>>>(s0, prices, b1, g1, be1,
                                                b2, g2, be2, bo, (float*)d_out);
}